// round 1
// baseline (speedup 1.0000x reference)
#include <cuda_runtime.h>
#include <math.h>

// Problem constants
#define NN    6144
#define DD    128
#define NCLS  20
#define NB    5

// Tiling
#define ITILES 48      // 6144 / 128 i-tiles
#define JSPLIT 12      // j-range split across blocks
#define JT_PER 4       // 48 j-tiles / JSPLIT

// Scratch (device globals: no allocation allowed)
__device__ float g_xn[NN * DD];                 // normalized rows
__device__ float g_part[JSPLIT * NN * 4];       // per-split partial row sums (pos_t,neg_t,pos_b,neg_b)
__device__ float g_loss_t[NN];
__device__ float g_loss_b[NN];

// ---------------------------------------------------------------------------
// Kernel 1: row-normalize x -> g_xn.  One warp per row.
// ---------------------------------------------------------------------------
__global__ void k_norm(const float* __restrict__ x) {
    int row  = blockIdx.x * 8 + (threadIdx.x >> 5);
    int lane = threadIdx.x & 31;
    if (row >= NN) return;
    float4 v = *(const float4*)(x + (size_t)row * DD + lane * 4);
    float s = v.x * v.x + v.y * v.y + v.z * v.z + v.w * v.w;
    #pragma unroll
    for (int o = 16; o; o >>= 1) s += __shfl_xor_sync(0xffffffffu, s, o);
    float nrm = fmaxf(sqrtf(s), 1e-8f);
    float inv = 1.0f / nrm;
    float4 o4 = make_float4(v.x * inv, v.y * inv, v.z * inv, v.w * inv);
    *(float4*)(g_xn + (size_t)row * DD + lane * 4) = o4;
}

// ---------------------------------------------------------------------------
// Kernel 2: fused tiled GEMM + masked exp row-sums.
// Block = 256 threads (16x16), tile 128x128, micro 8x8 (split fragments at +64).
// Smem tiles stored k-major: T[k][row] so fragment loads are float4,
// broadcast (A) / conflict-light (B).
// Grid: (48 i-tiles, 12 j-splits); each block handles 4 j-tiles.
// ---------------------------------------------------------------------------
__global__ void __launch_bounds__(256, 1)
k_main(const float* __restrict__ d_temp,
       const int*   __restrict__ targets,
       const int*   __restrict__ batch0) {
    extern __shared__ float sm[];
    float* As = sm;            // [128][128] k-major
    float* Bs = sm + 16384;    // [128][128] k-major

    const int tid = threadIdx.x;
    const int tx = tid & 15;
    const int ty = tid >> 4;
    const int ib    = blockIdx.x;
    const int split = blockIdx.y;
    const int ibase = ib * 128;

    const float t     = fminf(fmaxf(d_temp[0], 0.1f), 1.0f);
    const float inv_t = 1.0f / t;
    const float inv_b = 2.0f;      // 1 / TEMP_BATCH

    // Row identities for this thread's 8 rows
    int ri_g[8]; int ti[8]; int bi[8];
    #pragma unroll
    for (int rg = 0; rg < 2; rg++) {
        #pragma unroll
        for (int r = 0; r < 4; r++) {
            int row = ibase + rg * 64 + ty * 4 + r;
            ri_g[rg * 4 + r] = row;
            ti[rg * 4 + r]   = targets[row];
            bi[rg * 4 + r]   = batch0[row];
        }
    }

    // Load A tile once (transpose to k-major in smem; writes stride-1 -> conflict-free)
    {
        const float4* src = (const float4*)(g_xn + (size_t)ibase * DD);
        for (int idx = tid; idx < 128 * 32; idx += 256) {
            int row = idx & 127, k4 = idx >> 7;
            float4 v = src[row * 32 + k4];
            int k = k4 * 4;
            As[(k + 0) * 128 + row] = v.x;
            As[(k + 1) * 128 + row] = v.y;
            As[(k + 2) * 128 + row] = v.z;
            As[(k + 3) * 128 + row] = v.w;
        }
    }

    float pos_t[8], neg_t[8], pos_b[8], neg_b[8];
    #pragma unroll
    for (int r = 0; r < 8; r++) { pos_t[r] = 0.f; neg_t[r] = 0.f; pos_b[r] = 0.f; neg_b[r] = 0.f; }

    for (int q = 0; q < JT_PER; q++) {
        const int jt    = split * JT_PER + q;
        const int jbase = jt * 128;

        __syncthreads();   // protects Bs reuse (and orders As writes on iter 0)
        {
            const float4* src = (const float4*)(g_xn + (size_t)jbase * DD);
            for (int idx = tid; idx < 128 * 32; idx += 256) {
                int row = idx & 127, k4 = idx >> 7;
                float4 v = src[row * 32 + k4];
                int k = k4 * 4;
                Bs[(k + 0) * 128 + row] = v.x;
                Bs[(k + 1) * 128 + row] = v.y;
                Bs[(k + 2) * 128 + row] = v.z;
                Bs[(k + 3) * 128 + row] = v.w;
            }
        }
        __syncthreads();

        float acc[8][8];
        #pragma unroll
        for (int i = 0; i < 8; i++)
            #pragma unroll
            for (int j = 0; j < 8; j++) acc[i][j] = 0.f;

        #pragma unroll 8
        for (int k = 0; k < 128; k++) {
            float4 a0 = *(const float4*)&As[k * 128 + ty * 4];
            float4 a1 = *(const float4*)&As[k * 128 + 64 + ty * 4];
            float4 b0 = *(const float4*)&Bs[k * 128 + tx * 4];
            float4 b1 = *(const float4*)&Bs[k * 128 + 64 + tx * 4];
            float a[8] = {a0.x, a0.y, a0.z, a0.w, a1.x, a1.y, a1.z, a1.w};
            float b[8] = {b0.x, b0.y, b0.z, b0.w, b1.x, b1.y, b1.z, b1.w};
            #pragma unroll
            for (int i = 0; i < 8; i++)
                #pragma unroll
                for (int j = 0; j < 8; j++)
                    acc[i][j] = fmaf(a[i], b[j], acc[i][j]);
        }

        // Fused epilogue: masked exp sums
        #pragma unroll
        for (int cj = 0; cj < 8; cj++) {
            int jcol = jbase + ((cj >= 4) ? 64 : 0) + tx * 4 + (cj & 3);
            int tj = targets[jcol];
            int bj = batch0[jcol];
            #pragma unroll
            for (int rI = 0; rI < 8; rI++) {
                float s  = acc[rI][cj];
                float et = __expf(s * inv_t);
                float eb = __expf(s * inv_b);
                bool same_t = (tj == ti[rI]);
                bool self   = (jcol == ri_g[rI]);
                if (same_t) {
                    if (!self) {
                        pos_t[rI] += et;
                        if (bj == bi[rI]) pos_b[rI] += eb;
                        else              neg_b[rI] += eb;
                    }
                } else {
                    neg_t[rI] += et;
                }
            }
        }
    }

    // Reduce across the 16 tx lanes (within half-warp), write partials
    #pragma unroll
    for (int rI = 0; rI < 8; rI++) {
        float a = pos_t[rI], b = neg_t[rI], c = pos_b[rI], d = neg_b[rI];
        #pragma unroll
        for (int o = 8; o; o >>= 1) {
            a += __shfl_xor_sync(0xffffffffu, a, o);
            b += __shfl_xor_sync(0xffffffffu, b, o);
            c += __shfl_xor_sync(0xffffffffu, c, o);
            d += __shfl_xor_sync(0xffffffffu, d, o);
        }
        if (tx == 0) {
            float4 v = make_float4(a, b, c, d);
            *(float4*)(g_part + ((size_t)split * NN + ri_g[rI]) * 4) = v;
        }
    }
}

// ---------------------------------------------------------------------------
// Kernel 3: histograms, per-row loss, deterministic class means, final scalar.
// Single block, 1024 threads.
// ---------------------------------------------------------------------------
__global__ void k_final(const float* __restrict__ w_t,
                        const float* __restrict__ w_b,
                        const int*   __restrict__ targets,
                        const int*   __restrict__ batch0,
                        float*       __restrict__ out) {
    __shared__ int   hist_t[NCLS];
    __shared__ int   hist_tb[NCLS * NB];
    __shared__ float cls_sum_t[NCLS], cls_cnt_t[NCLS];
    __shared__ float cls_sum_b[NB],   cls_cnt_b[NB];

    int tid = threadIdx.x;
    if (tid < NCLS)      hist_t[tid]  = 0;
    if (tid < NCLS * NB) hist_tb[tid] = 0;
    __syncthreads();

    for (int i = tid; i < NN; i += blockDim.x) {
        int tcl = targets[i], bcl = batch0[i];
        atomicAdd(&hist_t[tcl], 1);
        atomicAdd(&hist_tb[tcl * NB + bcl], 1);
    }
    __syncthreads();

    // Per-row losses
    for (int i = tid; i < NN; i += blockDim.x) {
        float pt = 0.f, nt = 0.f, pb = 0.f, nb = 0.f;
        #pragma unroll
        for (int s = 0; s < JSPLIT; s++) {
            float4 v = *(const float4*)(g_part + ((size_t)s * NN + i) * 4);
            pt += v.x; nt += v.y; pb += v.z; nb += v.w;
        }
        int tcl = targets[i], bcl = batch0[i];
        int cp = hist_t[tcl];            // includes self
        int cn = NN - cp;
        bool valid_t = (cp >= 2) && (cn >= 1);
        g_loss_t[i] = valid_t ? logf((pt + nt) / pt) : 0.0f;

        int cpb = hist_tb[tcl * NB + bcl];   // includes self
        int cnb = cp - cpb;
        bool valid_b = (cpb >= 2) && (cnb >= 1);
        float lbr = logf((pb + nb) / pb);
        g_loss_b[i] = valid_b ? (1.0f / lbr) : 0.0f;
    }
    __syncthreads();

    // Deterministic per-class sums: one warp per class
    int wid = tid >> 5, lane = tid & 31;
    if (wid < NCLS) {
        int cp = hist_t[wid];
        bool valid = (cp >= 2) && ((NN - cp) >= 1);
        float s = 0.f, c = 0.f;
        for (int i = lane; i < NN; i += 32) {
            if (targets[i] == wid && valid) { s += g_loss_t[i]; c += 1.0f; }
        }
        #pragma unroll
        for (int o = 16; o; o >>= 1) {
            s += __shfl_xor_sync(0xffffffffu, s, o);
            c += __shfl_xor_sync(0xffffffffu, c, o);
        }
        if (lane == 0) { cls_sum_t[wid] = s; cls_cnt_t[wid] = c; }
    } else if (wid < NCLS + NB) {
        int bc = wid - NCLS;
        float s = 0.f, c = 0.f;
        for (int i = lane; i < NN; i += 32) {
            if (batch0[i] == bc) {
                int tcl = targets[i];
                int cpb = hist_tb[tcl * NB + bc];
                int cnb = hist_t[tcl] - cpb;
                bool valid = (cpb >= 2) && (cnb >= 1);
                if (valid) { s += g_loss_b[i]; c += 1.0f; }
            }
        }
        #pragma unroll
        for (int o = 16; o; o >>= 1) {
            s += __shfl_xor_sync(0xffffffffu, s, o);
            c += __shfl_xor_sync(0xffffffffu, c, o);
        }
        if (lane == 0) { cls_sum_b[bc] = s; cls_cnt_b[bc] = c; }
    }
    __syncthreads();

    if (tid == 0) {
        float lt = 0.f;
        for (int cI = 0; cI < NCLS; cI++) {
            float cnt  = cls_cnt_t[cI];
            float mean = cls_sum_t[cI] / fmaxf(cnt, 1.0f);
            if (cnt > 0.f) lt += mean * w_t[cI];
        }
        float lb = 0.f;
        for (int cI = 0; cI < NB; cI++) {
            float cnt  = cls_cnt_b[cI];
            float mean = cls_sum_b[cI] / fmaxf(cnt, 1.0f);
            if (cnt > 0.f) lb += mean * w_b[cI];
        }
        out[0] = 0.9f * lt + 0.1f * lb;
    }
}

// ---------------------------------------------------------------------------
extern "C" void kernel_launch(void* const* d_in, const int* in_sizes, int n_in,
                              void* d_out, int out_size) {
    const float* x       = (const float*)d_in[0];
    const float* temp    = (const float*)d_in[1];
    const float* w_t     = (const float*)d_in[2];
    const float* w_b     = (const float*)d_in[3];
    const int*   targets = (const int*)d_in[4];
    const int*   batch0  = (const int*)d_in[5];
    float*       out     = (float*)d_out;

    k_norm<<<NN / 8, 256>>>(x);

    cudaFuncSetAttribute(k_main, cudaFuncAttributeMaxDynamicSharedMemorySize, 128 * 1024);
    dim3 grid(ITILES, JSPLIT);
    k_main<<<grid, 256, 128 * 1024>>>(temp, targets, batch0);

    k_final<<<1, 1024>>>(w_t, w_b, targets, batch0, out);
}

// round 2
// speedup vs baseline: 1.0427x; 1.0427x over previous
#include <cuda_runtime.h>
#include <math.h>

// Problem constants
#define NN    6144
#define DD    128
#define NCLS  20
#define NB    5

// Tiling
#define ITILES 48      // 6144 / 128 i-tiles
#define JSPLIT 12      // j-range split across blocks
#define JT_PER 4       // 48 j-tiles / JSPLIT

// Packed f32x2 helpers (sm_103a FFMA2 — only reachable via PTX)
#define FMA2(acc, a, b) \
    asm("fma.rn.f32x2 %0, %1, %2, %0;" : "+l"(acc) : "l"(a), "l"(b))
#define DUP2(out, f) \
    asm("mov.b64 %0, {%1, %1};" : "=l"(out) : "r"(__float_as_uint(f)))
#define UNPK2(lo, hi, in) \
    asm("mov.b64 {%0, %1}, %2;" : "=f"(lo), "=f"(hi) : "l"(in))

// Scratch (device globals: no allocation allowed)
__device__ float g_xn[NN * DD];                 // normalized rows
__device__ float g_part[JSPLIT * NN * 4];       // per-split partials (pos_t,neg_t,pos_b,neg_b)
__device__ float g_loss_t[NN];
__device__ float g_loss_b[NN];

// ---------------------------------------------------------------------------
// Kernel 1: row-normalize x -> g_xn.  One warp per row.
// ---------------------------------------------------------------------------
__global__ void k_norm(const float* __restrict__ x) {
    int row  = blockIdx.x * 8 + (threadIdx.x >> 5);
    int lane = threadIdx.x & 31;
    if (row >= NN) return;
    float4 v = *(const float4*)(x + (size_t)row * DD + lane * 4);
    float s = v.x * v.x + v.y * v.y + v.z * v.z + v.w * v.w;
    #pragma unroll
    for (int o = 16; o; o >>= 1) s += __shfl_xor_sync(0xffffffffu, s, o);
    float nrm = fmaxf(sqrtf(s), 1e-8f);
    float inv = 1.0f / nrm;
    float4 o4 = make_float4(v.x * inv, v.y * inv, v.z * inv, v.w * inv);
    *(float4*)(g_xn + (size_t)row * DD + lane * 4) = o4;
}

// ---------------------------------------------------------------------------
// Kernel 2: fused tiled GEMM (packed f32x2) + masked exp row-sums.
// Block = 256 threads (16x16), tile 128x128, micro 8x8 (split fragments +64).
// Accumulators packed pairwise along j: acc2[8][4] (f32x2 in 64-bit regs).
// ---------------------------------------------------------------------------
__global__ void __launch_bounds__(256, 1)
k_main(const float* __restrict__ d_temp,
       const int*   __restrict__ targets,
       const int*   __restrict__ batch0) {
    extern __shared__ float sm[];
    float* As = sm;            // [128][128] k-major
    float* Bs = sm + 16384;    // [128][128] k-major

    const int tid = threadIdx.x;
    const int tx = tid & 15;
    const int ty = tid >> 4;
    const int ib    = blockIdx.x;
    const int split = blockIdx.y;
    const int ibase = ib * 128;

    const float t     = fminf(fmaxf(d_temp[0], 0.1f), 1.0f);
    const float inv_t = 1.0f / t;
    const float inv_b = 2.0f;      // 1 / TEMP_BATCH

    // Row identities for this thread's 8 rows
    int ri_g[8]; int ti[8]; int bi[8];
    #pragma unroll
    for (int rg = 0; rg < 2; rg++) {
        #pragma unroll
        for (int r = 0; r < 4; r++) {
            int row = ibase + rg * 64 + ty * 4 + r;
            ri_g[rg * 4 + r] = row;
            ti[rg * 4 + r]   = targets[row];
            bi[rg * 4 + r]   = batch0[row];
        }
    }

    // Load A tile once (transpose to k-major in smem)
    {
        const float4* src = (const float4*)(g_xn + (size_t)ibase * DD);
        for (int idx = tid; idx < 128 * 32; idx += 256) {
            int row = idx & 127, k4 = idx >> 7;
            float4 v = src[row * 32 + k4];
            int k = k4 * 4;
            As[(k + 0) * 128 + row] = v.x;
            As[(k + 1) * 128 + row] = v.y;
            As[(k + 2) * 128 + row] = v.z;
            As[(k + 3) * 128 + row] = v.w;
        }
    }

    float pos_t[8], neg_t[8], pos_b[8], neg_b[8];
    #pragma unroll
    for (int r = 0; r < 8; r++) { pos_t[r] = 0.f; neg_t[r] = 0.f; pos_b[r] = 0.f; neg_b[r] = 0.f; }

    for (int q = 0; q < JT_PER; q++) {
        const int jt    = split * JT_PER + q;
        const int jbase = jt * 128;

        __syncthreads();   // protects Bs reuse (and orders As writes on iter 0)
        {
            const float4* src = (const float4*)(g_xn + (size_t)jbase * DD);
            for (int idx = tid; idx < 128 * 32; idx += 256) {
                int row = idx & 127, k4 = idx >> 7;
                float4 v = src[row * 32 + k4];
                int k = k4 * 4;
                Bs[(k + 0) * 128 + row] = v.x;
                Bs[(k + 1) * 128 + row] = v.y;
                Bs[(k + 2) * 128 + row] = v.z;
                Bs[(k + 3) * 128 + row] = v.w;
            }
        }
        __syncthreads();

        // Packed accumulators: acc2[i][p] holds columns (p*2, p*2+1) of the
        // 8-wide j fragment (p=0,1 -> cols tx*4+{0..3}; p=2,3 -> 64+tx*4+{0..3})
        unsigned long long acc2[8][4];
        #pragma unroll
        for (int i = 0; i < 8; i++)
            #pragma unroll
            for (int p = 0; p < 4; p++) acc2[i][p] = 0ull;

        #pragma unroll 4
        for (int k = 0; k < 128; k++) {
            // B fragment: directly as 64-bit packed pairs (16B-aligned)
            ulonglong2 b0 = *(const ulonglong2*)&Bs[k * 128 + tx * 4];
            ulonglong2 b1 = *(const ulonglong2*)&Bs[k * 128 + 64 + tx * 4];
            unsigned long long bp[4] = {b0.x, b0.y, b1.x, b1.y};
            // A fragment: scalars, duplicated into f32x2
            float4 a0 = *(const float4*)&As[k * 128 + ty * 4];
            float4 a1 = *(const float4*)&As[k * 128 + 64 + ty * 4];
            float a[8] = {a0.x, a0.y, a0.z, a0.w, a1.x, a1.y, a1.z, a1.w};
            unsigned long long ad[8];
            #pragma unroll
            for (int i = 0; i < 8; i++) DUP2(ad[i], a[i]);
            #pragma unroll
            for (int i = 0; i < 8; i++)
                #pragma unroll
                for (int p = 0; p < 4; p++)
                    FMA2(acc2[i][p], ad[i], bp[p]);
        }

        // Fused epilogue: masked exp sums
        #pragma unroll
        for (int p = 0; p < 4; p++) {
            #pragma unroll
            for (int l = 0; l < 2; l++) {
                int jcol = jbase + ((p >= 2) ? 64 : 0) + tx * 4 + (p & 1) * 2 + l;
                int tj = targets[jcol];
                int bj = batch0[jcol];
                #pragma unroll
                for (int rI = 0; rI < 8; rI++) {
                    float slo, shi;
                    UNPK2(slo, shi, acc2[rI][p]);
                    float s = l ? shi : slo;
                    float et = __expf(s * inv_t);
                    float eb = __expf(s * inv_b);
                    bool same_t = (tj == ti[rI]);
                    bool self   = (jcol == ri_g[rI]);
                    if (same_t) {
                        if (!self) {
                            pos_t[rI] += et;
                            if (bj == bi[rI]) pos_b[rI] += eb;
                            else              neg_b[rI] += eb;
                        }
                    } else {
                        neg_t[rI] += et;
                    }
                }
            }
        }
    }

    // Reduce across the 16 tx lanes (within half-warp), write partials
    #pragma unroll
    for (int rI = 0; rI < 8; rI++) {
        float a = pos_t[rI], b = neg_t[rI], c = pos_b[rI], d = neg_b[rI];
        #pragma unroll
        for (int o = 8; o; o >>= 1) {
            a += __shfl_xor_sync(0xffffffffu, a, o);
            b += __shfl_xor_sync(0xffffffffu, b, o);
            c += __shfl_xor_sync(0xffffffffu, c, o);
            d += __shfl_xor_sync(0xffffffffu, d, o);
        }
        if (tx == 0) {
            float4 v = make_float4(a, b, c, d);
            *(float4*)(g_part + ((size_t)split * NN + ri_g[rI]) * 4) = v;
        }
    }
}

// ---------------------------------------------------------------------------
// Kernel 3: histograms, per-row loss, deterministic class means, final scalar.
// ---------------------------------------------------------------------------
__global__ void k_final(const float* __restrict__ w_t,
                        const float* __restrict__ w_b,
                        const int*   __restrict__ targets,
                        const int*   __restrict__ batch0,
                        float*       __restrict__ out) {
    __shared__ int   hist_t[NCLS];
    __shared__ int   hist_tb[NCLS * NB];
    __shared__ float cls_sum_t[NCLS], cls_cnt_t[NCLS];
    __shared__ float cls_sum_b[NB],   cls_cnt_b[NB];

    int tid = threadIdx.x;
    if (tid < NCLS)      hist_t[tid]  = 0;
    if (tid < NCLS * NB) hist_tb[tid] = 0;
    __syncthreads();

    for (int i = tid; i < NN; i += blockDim.x) {
        int tcl = targets[i], bcl = batch0[i];
        atomicAdd(&hist_t[tcl], 1);
        atomicAdd(&hist_tb[tcl * NB + bcl], 1);
    }
    __syncthreads();

    for (int i = tid; i < NN; i += blockDim.x) {
        float pt = 0.f, nt = 0.f, pb = 0.f, nb = 0.f;
        #pragma unroll
        for (int s = 0; s < JSPLIT; s++) {
            float4 v = *(const float4*)(g_part + ((size_t)s * NN + i) * 4);
            pt += v.x; nt += v.y; pb += v.z; nb += v.w;
        }
        int tcl = targets[i], bcl = batch0[i];
        int cp = hist_t[tcl];            // includes self
        int cn = NN - cp;
        bool valid_t = (cp >= 2) && (cn >= 1);
        g_loss_t[i] = valid_t ? logf((pt + nt) / pt) : 0.0f;

        int cpb = hist_tb[tcl * NB + bcl];   // includes self
        int cnb = cp - cpb;
        bool valid_b = (cpb >= 2) && (cnb >= 1);
        float lbr = logf((pb + nb) / pb);
        g_loss_b[i] = valid_b ? (1.0f / lbr) : 0.0f;
    }
    __syncthreads();

    int wid = tid >> 5, lane = tid & 31;
    if (wid < NCLS) {
        int cp = hist_t[wid];
        bool valid = (cp >= 2) && ((NN - cp) >= 1);
        float s = 0.f, c = 0.f;
        for (int i = lane; i < NN; i += 32) {
            if (targets[i] == wid && valid) { s += g_loss_t[i]; c += 1.0f; }
        }
        #pragma unroll
        for (int o = 16; o; o >>= 1) {
            s += __shfl_xor_sync(0xffffffffu, s, o);
            c += __shfl_xor_sync(0xffffffffu, c, o);
        }
        if (lane == 0) { cls_sum_t[wid] = s; cls_cnt_t[wid] = c; }
    } else if (wid < NCLS + NB) {
        int bc = wid - NCLS;
        float s = 0.f, c = 0.f;
        for (int i = lane; i < NN; i += 32) {
            if (batch0[i] == bc) {
                int tcl = targets[i];
                int cpb = hist_tb[tcl * NB + bc];
                int cnb = hist_t[tcl] - cpb;
                bool valid = (cpb >= 2) && (cnb >= 1);
                if (valid) { s += g_loss_b[i]; c += 1.0f; }
            }
        }
        #pragma unroll
        for (int o = 16; o; o >>= 1) {
            s += __shfl_xor_sync(0xffffffffu, s, o);
            c += __shfl_xor_sync(0xffffffffu, c, o);
        }
        if (lane == 0) { cls_sum_b[bc] = s; cls_cnt_b[bc] = c; }
    }
    __syncthreads();

    if (tid == 0) {
        float lt = 0.f;
        for (int cI = 0; cI < NCLS; cI++) {
            float cnt  = cls_cnt_t[cI];
            float mean = cls_sum_t[cI] / fmaxf(cnt, 1.0f);
            if (cnt > 0.f) lt += mean * w_t[cI];
        }
        float lb = 0.f;
        for (int cI = 0; cI < NB; cI++) {
            float cnt  = cls_cnt_b[cI];
            float mean = cls_sum_b[cI] / fmaxf(cnt, 1.0f);
            if (cnt > 0.f) lb += mean * w_b[cI];
        }
        out[0] = 0.9f * lt + 0.1f * lb;
    }
}

// ---------------------------------------------------------------------------
extern "C" void kernel_launch(void* const* d_in, const int* in_sizes, int n_in,
                              void* d_out, int out_size) {
    const float* x       = (const float*)d_in[0];
    const float* temp    = (const float*)d_in[1];
    const float* w_t     = (const float*)d_in[2];
    const float* w_b     = (const float*)d_in[3];
    const int*   targets = (const int*)d_in[4];
    const int*   batch0  = (const int*)d_in[5];
    float*       out     = (float*)d_out;

    k_norm<<<NN / 8, 256>>>(x);

    cudaFuncSetAttribute(k_main, cudaFuncAttributeMaxDynamicSharedMemorySize, 128 * 1024);
    dim3 grid(ITILES, JSPLIT);
    k_main<<<grid, 256, 128 * 1024>>>(temp, targets, batch0);

    k_final<<<1, 1024>>>(w_t, w_b, targets, batch0, out);
}

// round 4
// speedup vs baseline: 1.2720x; 1.2199x over previous
#include <cuda_runtime.h>
#include <cuda_bf16.h>
#include <math.h>
#include <stdint.h>

// Problem constants
#define NN    6144
#define DD    128
#define NCLS  20
#define NB    5

// Tiling
#define ITILES 48      // 6144/128 i-tiles
#define JSPLIT 3       // j splits -> grid 48*3 = 144 CTAs (1 wave, 1 CTA/SM)
#define JT_PER 16      // j-tiles per CTA

// SMEM byte offsets (dynamic). Rows are 256B (128 bf16), 16B-chunk XOR swizzle.
#define OFF_AHI 0
#define OFF_ALO 32768
#define OFF_BHI 65536
#define OFF_BLO 98304
#define OFF_TJ  131072
#define OFF_BJ  (OFF_TJ + 512)
#define OFF_RED (OFF_BJ + 512)            // 4 warps-n x 128 rows x 4 floats
#define SMEM_TOTAL (OFF_RED + 8192)       // ~139.5 KB -> 1 CTA/SM

__device__ __forceinline__ uint32_t smem_u32(const void* p) {
    uint32_t a;
    asm("{ .reg .u64 t; cvta.to.shared.u64 t, %1; cvt.u32.u64 %0, t; }" : "=r"(a) : "l"(p));
    return a;
}

#define LDSM_X4(r0, r1, r2, r3, addr) \
    asm volatile("ldmatrix.sync.aligned.m8n8.x4.shared.b16 {%0,%1,%2,%3}, [%4];" \
                 : "=r"(r0), "=r"(r1), "=r"(r2), "=r"(r3) : "r"(addr))

#define MMA_BF16(c, a, b0, b1) \
    asm volatile("mma.sync.aligned.m16n8k16.row.col.f32.bf16.bf16.f32 " \
                 "{%0,%1,%2,%3}, {%4,%5,%6,%7}, {%8,%9}, {%0,%1,%2,%3};" \
                 : "+f"((c)[0]), "+f"((c)[1]), "+f"((c)[2]), "+f"((c)[3]) \
                 : "r"((a)[0]), "r"((a)[1]), "r"((a)[2]), "r"((a)[3]), "r"(b0), "r"(b1))

// ---------------- Scratch (device globals) ----------------
__device__ __nv_bfloat16 g_hi[NN * DD];
__device__ __nv_bfloat16 g_lo[NN * DD];
__device__ float g_part[JSPLIT * NN * 4];
__device__ float g_loss_t[NN];
__device__ float g_loss_b[NN];

// ---------------------------------------------------------------------------
// Kernel 1: normalize + bf16 hi/lo split.  One warp per row.
// ---------------------------------------------------------------------------
__global__ void k_norm(const float* __restrict__ x) {
    int row  = blockIdx.x * 8 + (threadIdx.x >> 5);
    int lane = threadIdx.x & 31;
    if (row >= NN) return;
    float4 v = *(const float4*)(x + (size_t)row * DD + lane * 4);
    float s = v.x * v.x + v.y * v.y + v.z * v.z + v.w * v.w;
    #pragma unroll
    for (int o = 16; o; o >>= 1) s += __shfl_xor_sync(0xffffffffu, s, o);
    float inv = 1.0f / fmaxf(sqrtf(s), 1e-8f);
    float f[4] = {v.x * inv, v.y * inv, v.z * inv, v.w * inv};
    __nv_bfloat16 h[4], l[4];
    #pragma unroll
    for (int e = 0; e < 4; e++) {
        h[e] = __float2bfloat16(f[e]);
        l[e] = __float2bfloat16(f[e] - __bfloat162float(h[e]));
    }
    size_t base = (size_t)row * DD + lane * 4;
    *(__nv_bfloat162*)(g_hi + base)     = __nv_bfloat162(h[0], h[1]);
    *(__nv_bfloat162*)(g_hi + base + 2) = __nv_bfloat162(h[2], h[3]);
    *(__nv_bfloat162*)(g_lo + base)     = __nv_bfloat162(l[0], l[1]);
    *(__nv_bfloat162*)(g_lo + base + 2) = __nv_bfloat162(l[2], l[3]);
}

// ---------------------------------------------------------------------------
// Kernel 2: HMMA bf16 split-GEMM (hi*hi + hi*lo + lo*hi) + fused epilogue.
// 256 threads = 8 warps in 2(m) x 4(n); warp tile 64x32 (m16n8k16 frags).
// ---------------------------------------------------------------------------
__device__ __forceinline__ void fill_tile(char* smem, int off,
                                          const __nv_bfloat16* __restrict__ src,
                                          int rowbase, int tid) {
    #pragma unroll
    for (int it = 0; it < 8; it++) {
        int lin = it * 256 + tid;          // 0..2047
        int n   = lin >> 4;                // tile row 0..127
        int c16 = lin & 15;                // 16B chunk along k
        uint4 v = *(const uint4*)(src + (size_t)(rowbase + n) * DD + c16 * 8);
        *(uint4*)(smem + off + n * 256 + ((c16 ^ (n & 7)) << 4)) = v;
    }
}

__global__ void __launch_bounds__(256, 1)
k_main(const float* __restrict__ d_temp,
       const int*   __restrict__ targets,
       const int*   __restrict__ batch0) {
    extern __shared__ char smem[];
    const uint32_t sb = smem_u32(smem);
    const int tid = threadIdx.x;
    const int L   = tid & 31;
    const int w   = tid >> 5;
    const int wm  = w & 1;          // 0..1 (m)
    const int wn  = w >> 1;         // 0..3 (n)
    const int ibase = blockIdx.x * 128;
    const int split = blockIdx.y;

    int*   sm_tj = (int*)(smem + OFF_TJ);
    int*   sm_bj = (int*)(smem + OFF_BJ);
    float* red   = (float*)(smem + OFF_RED);

    const float t     = fminf(fmaxf(d_temp[0], 0.1f), 1.0f);
    const float inv_t = 1.0f / t;

    // A tiles (hi & lo) resident in smem
    fill_tile(smem, OFF_AHI, g_hi, ibase, tid);
    fill_tile(smem, OFF_ALO, g_lo, ibase, tid);

    // Row identities for this thread's 8 accumulator rows
    const int g = L >> 2, q = L & 3;
    int rg[8], ti_[8], bi_[8];
    #pragma unroll
    for (int p = 0; p < 8; p++) {
        int mi = p >> 1, h = p & 1;
        int row_loc = wm * 64 + mi * 16 + h * 8 + g;
        rg[p]  = ibase + row_loc;
        ti_[p] = targets[rg[p]];
        bi_[p] = batch0[rg[p]];
    }
    float pt[8], nt[8], pb[8], nb[8];
    #pragma unroll
    for (int p = 0; p < 8; p++) { pt[p] = 0.f; nt[p] = 0.f; pb[p] = 0.f; nb[p] = 0.f; }

    // ldmatrix per-lane row/chunk components
    const int la15 = L & 15;                       // A row offset within 16
    const int l4   = L >> 4;                       // A k-chunk selector
    const int lb7  = (L & 7) + ((L >> 4) << 3);    // B row offset within 16
    const int lb1  = (L >> 3) & 1;                 // B k-chunk selector

    for (int qt = 0; qt < JT_PER; qt++) {
        const int jbase = (split * JT_PER + qt) * 128;
        __syncthreads();                            // B smem reuse (also orders A fill)
        fill_tile(smem, OFF_BHI, g_hi, jbase, tid);
        fill_tile(smem, OFF_BLO, g_lo, jbase, tid);
        if (tid < 128) { sm_tj[tid] = targets[jbase + tid]; sm_bj[tid] = batch0[jbase + tid]; }
        __syncthreads();

        float acc[4][4][4];
        #pragma unroll
        for (int mi = 0; mi < 4; mi++)
            #pragma unroll
            for (int ni = 0; ni < 4; ni++)
                #pragma unroll
                for (int e = 0; e < 4; e++) acc[mi][ni][e] = 0.f;

        #pragma unroll
        for (int pass = 0; pass < 3; pass++) {
            const uint32_t abase = sb + ((pass == 2) ? OFF_ALO : OFF_AHI);
            const uint32_t bbase = sb + ((pass == 1) ? OFF_BLO : OFF_BHI);
            #pragma unroll
            for (int ks = 0; ks < 8; ks++) {
                uint32_t a[4][4], b[2][4];
                #pragma unroll
                for (int mi = 0; mi < 4; mi++) {
                    int rowA = wm * 64 + mi * 16 + la15;
                    uint32_t ad = abase + rowA * 256 + (((ks * 2 + l4) ^ (rowA & 7)) << 4);
                    LDSM_X4(a[mi][0], a[mi][1], a[mi][2], a[mi][3], ad);
                }
                #pragma unroll
                for (int np = 0; np < 2; np++) {
                    int rowB = wn * 32 + np * 16 + lb7;
                    uint32_t bd = bbase + rowB * 256 + (((ks * 2 + lb1) ^ (rowB & 7)) << 4);
                    LDSM_X4(b[np][0], b[np][1], b[np][2], b[np][3], bd);
                }
                #pragma unroll
                for (int mi = 0; mi < 4; mi++)
                    #pragma unroll
                    for (int ni = 0; ni < 4; ni++)
                        MMA_BF16(acc[mi][ni], a[mi],
                                 b[ni >> 1][(ni & 1) * 2], b[ni >> 1][(ni & 1) * 2 + 1]);
            }
        }

        // Fused epilogue: exp + masked accumulation into register partials
        #pragma unroll
        for (int mi = 0; mi < 4; mi++) {
            #pragma unroll
            for (int ni = 0; ni < 4; ni++) {
                int j0 = wn * 32 + ni * 8 + 2 * q;
                #pragma unroll
                for (int e = 0; e < 4; e++) {
                    int p  = mi * 2 + (e >> 1);
                    int jl = j0 + (e & 1);
                    float s  = acc[mi][ni][e];
                    float et = __expf(s * inv_t);
                    if (sm_tj[jl] == ti_[p]) {
                        if (jbase + jl != rg[p]) {
                            pt[p] += et;
                            float eb = __expf(s * 2.0f);   // 1/TEMP_BATCH = 2
                            if (sm_bj[jl] == bi_[p]) pb[p] += eb;
                            else                     nb[p] += eb;
                        }
                    } else {
                        nt[p] += et;
                    }
                }
            }
        }
    }

    // Deterministic reduction: 4 lanes (q) share a row -> shfl; then 4 n-warps via smem
    #pragma unroll
    for (int p = 0; p < 8; p++) {
        float a = pt[p], b = nt[p], c = pb[p], d = nb[p];
        #pragma unroll
        for (int o = 1; o <= 2; o <<= 1) {
            a += __shfl_xor_sync(0xffffffffu, a, o);
            b += __shfl_xor_sync(0xffffffffu, b, o);
            c += __shfl_xor_sync(0xffffffffu, c, o);
            d += __shfl_xor_sync(0xffffffffu, d, o);
        }
        if (q == 0) {
            int mi = p >> 1, h = p & 1;
            int row_loc = wm * 64 + mi * 16 + h * 8 + g;
            *(float4*)&red[(wn * 128 + row_loc) * 4] = make_float4(a, b, c, d);
        }
    }
    __syncthreads();
    if (tid < 128) {
        float a = 0.f, b = 0.f, c = 0.f, d = 0.f;
        #pragma unroll
        for (int v = 0; v < 4; v++) {
            float4 r4 = *(const float4*)&red[(v * 128 + tid) * 4];
            a += r4.x; b += r4.y; c += r4.z; d += r4.w;
        }
        *(float4*)(g_part + ((size_t)split * NN + ibase + tid) * 4) = make_float4(a, b, c, d);
    }
}

// ---------------------------------------------------------------------------
// Kernel 3: histograms, per-row loss, deterministic class means, final scalar.
// ---------------------------------------------------------------------------
__global__ void k_final(const float* __restrict__ w_t,
                        const float* __restrict__ w_b,
                        const int*   __restrict__ targets,
                        const int*   __restrict__ batch0,
                        float*       __restrict__ out) {
    __shared__ int   hist_t[NCLS];
    __shared__ int   hist_tb[NCLS * NB];
    __shared__ float cls_sum_t[NCLS], cls_cnt_t[NCLS];
    __shared__ float cls_sum_b[NB],   cls_cnt_b[NB];

    int tid = threadIdx.x;
    if (tid < NCLS)      hist_t[tid]  = 0;
    if (tid < NCLS * NB) hist_tb[tid] = 0;
    __syncthreads();

    for (int i = tid; i < NN; i += blockDim.x) {
        int tcl = targets[i], bcl = batch0[i];
        atomicAdd(&hist_t[tcl], 1);
        atomicAdd(&hist_tb[tcl * NB + bcl], 1);
    }
    __syncthreads();

    for (int i = tid; i < NN; i += blockDim.x) {
        float ptv = 0.f, ntv = 0.f, pbv = 0.f, nbv = 0.f;
        #pragma unroll
        for (int s = 0; s < JSPLIT; s++) {
            float4 v = *(const float4*)(g_part + ((size_t)s * NN + i) * 4);
            ptv += v.x; ntv += v.y; pbv += v.z; nbv += v.w;
        }
        int tcl = targets[i], bcl = batch0[i];
        int cp = hist_t[tcl];
        int cn = NN - cp;
        bool valid_t = (cp >= 2) && (cn >= 1);
        g_loss_t[i] = valid_t ? logf((ptv + ntv) / ptv) : 0.0f;

        int cpb = hist_tb[tcl * NB + bcl];
        int cnb = cp - cpb;
        bool valid_b = (cpb >= 2) && (cnb >= 1);
        float lbr = logf((pbv + nbv) / pbv);
        g_loss_b[i] = valid_b ? (1.0f / lbr) : 0.0f;
    }
    __syncthreads();

    int wid = tid >> 5, lane = tid & 31;
    if (wid < NCLS) {
        int cp = hist_t[wid];
        bool valid = (cp >= 2) && ((NN - cp) >= 1);
        float s = 0.f, c = 0.f;
        for (int i = lane; i < NN; i += 32) {
            if (targets[i] == wid && valid) { s += g_loss_t[i]; c += 1.0f; }
        }
        #pragma unroll
        for (int o = 16; o; o >>= 1) {
            s += __shfl_xor_sync(0xffffffffu, s, o);
            c += __shfl_xor_sync(0xffffffffu, c, o);
        }
        if (lane == 0) { cls_sum_t[wid] = s; cls_cnt_t[wid] = c; }
    } else if (wid < NCLS + NB) {
        int bc = wid - NCLS;
        float s = 0.f, c = 0.f;
        for (int i = lane; i < NN; i += 32) {
            if (batch0[i] == bc) {
                int tcl = targets[i];
                int cpb = hist_tb[tcl * NB + bc];
                int cnb = hist_t[tcl] - cpb;
                bool valid = (cpb >= 2) && (cnb >= 1);
                if (valid) { s += g_loss_b[i]; c += 1.0f; }
            }
        }
        #pragma unroll
        for (int o = 16; o; o >>= 1) {
            s += __shfl_xor_sync(0xffffffffu, s, o);
            c += __shfl_xor_sync(0xffffffffu, c, o);
        }
        if (lane == 0) { cls_sum_b[bc] = s; cls_cnt_b[bc] = c; }
    }
    __syncthreads();

    if (tid == 0) {
        float lt = 0.f;
        for (int cI = 0; cI < NCLS; cI++) {
            float cnt  = cls_cnt_t[cI];
            float mean = cls_sum_t[cI] / fmaxf(cnt, 1.0f);
            if (cnt > 0.f) lt += mean * w_t[cI];
        }
        float lb = 0.f;
        for (int cI = 0; cI < NB; cI++) {
            float cnt  = cls_cnt_b[cI];
            float mean = cls_sum_b[cI] / fmaxf(cnt, 1.0f);
            if (cnt > 0.f) lb += mean * w_b[cI];
        }
        out[0] = 0.9f * lt + 0.1f * lb;
    }
}

// ---------------------------------------------------------------------------
extern "C" void kernel_launch(void* const* d_in, const int* in_sizes, int n_in,
                              void* d_out, int out_size) {
    const float* x       = (const float*)d_in[0];
    const float* temp    = (const float*)d_in[1];
    const float* w_t     = (const float*)d_in[2];
    const float* w_b     = (const float*)d_in[3];
    const int*   targets = (const int*)d_in[4];
    const int*   batch0  = (const int*)d_in[5];
    float*       out     = (float*)d_out;

    k_norm<<<NN / 8, 256>>>(x);

    cudaFuncSetAttribute(k_main, cudaFuncAttributeMaxDynamicSharedMemorySize, SMEM_TOTAL);
    dim3 grid(ITILES, JSPLIT);
    k_main<<<grid, 256, SMEM_TOTAL>>>(temp, targets, batch0);

    k_final<<<1, 1024>>>(w_t, w_b, targets, batch0, out);
}

// round 5
// speedup vs baseline: 1.9451x; 1.5292x over previous
#include <cuda_runtime.h>
#include <cuda_bf16.h>
#include <math.h>
#include <stdint.h>

// Problem constants
#define NN    6144
#define DD    128
#define NCLS  20
#define NB    5

#define ITILES 48                   // 6144/128
#define NPAIRS (ITILES*(ITILES+1)/2)  // 1176 tile pairs (I<=J)
#define JSPLIT ITILES               // one partial buffer per peer tile

// SMEM byte offsets. Tile rows are 256B (128 bf16), 16B-chunk XOR swizzle.
#define OFF_AHI  0
#define OFF_ALO  32768
#define OFF_BHI  65536
#define OFF_BLO  98304
#define OFF_TI   131072
#define OFF_BI   (OFF_TI + 512)
#define OFF_TJ   (OFF_BI + 512)
#define OFF_BJ   (OFF_TJ + 512)
#define OFF_RED1 (OFF_BJ + 512)          // 4(wn) x 128 x float4 = 8KB
#define OFF_RED2 (OFF_RED1 + 8192)       // 2(wm) x 128 x float4 = 4KB
#define SMEM_TOTAL (OFF_RED2 + 4096)     // ~145.4 KB -> 1 CTA/SM

__device__ __forceinline__ uint32_t smem_u32(const void* p) {
    uint32_t a;
    asm("{ .reg .u64 t; cvta.to.shared.u64 t, %1; cvt.u32.u64 %0, t; }" : "=r"(a) : "l"(p));
    return a;
}

#define LDSM_X4(r0, r1, r2, r3, addr) \
    asm volatile("ldmatrix.sync.aligned.m8n8.x4.shared.b16 {%0,%1,%2,%3}, [%4];" \
                 : "=r"(r0), "=r"(r1), "=r"(r2), "=r"(r3) : "r"(addr))

#define MMA_BF16(c, a, b0, b1) \
    asm volatile("mma.sync.aligned.m16n8k16.row.col.f32.bf16.bf16.f32 " \
                 "{%0,%1,%2,%3}, {%4,%5,%6,%7}, {%8,%9}, {%0,%1,%2,%3};" \
                 : "+f"((c)[0]), "+f"((c)[1]), "+f"((c)[2]), "+f"((c)[3]) \
                 : "r"((a)[0]), "r"((a)[1]), "r"((a)[2]), "r"((a)[3]), "r"(b0), "r"(b1))

// ---------------- Scratch (device globals) ----------------
__device__ __nv_bfloat16 g_hi[NN * DD];
__device__ __nv_bfloat16 g_lo[NN * DD];
__device__ float g_part[JSPLIT * NN * 4];
__device__ float g_loss_t[NN];
__device__ float g_loss_b[NN];

// ---------------------------------------------------------------------------
// Kernel 1: normalize + bf16 hi/lo split.  One warp per row.
// ---------------------------------------------------------------------------
__global__ void k_norm(const float* __restrict__ x) {
    int row  = blockIdx.x * 8 + (threadIdx.x >> 5);
    int lane = threadIdx.x & 31;
    if (row >= NN) return;
    float4 v = *(const float4*)(x + (size_t)row * DD + lane * 4);
    float s = v.x * v.x + v.y * v.y + v.z * v.z + v.w * v.w;
    #pragma unroll
    for (int o = 16; o; o >>= 1) s += __shfl_xor_sync(0xffffffffu, s, o);
    float inv = 1.0f / fmaxf(sqrtf(s), 1e-8f);
    float f[4] = {v.x * inv, v.y * inv, v.z * inv, v.w * inv};
    __nv_bfloat16 h[4], l[4];
    #pragma unroll
    for (int e = 0; e < 4; e++) {
        h[e] = __float2bfloat16(f[e]);
        l[e] = __float2bfloat16(f[e] - __bfloat162float(h[e]));
    }
    size_t base = (size_t)row * DD + lane * 4;
    *(__nv_bfloat162*)(g_hi + base)     = __nv_bfloat162(h[0], h[1]);
    *(__nv_bfloat162*)(g_hi + base + 2) = __nv_bfloat162(h[2], h[3]);
    *(__nv_bfloat162*)(g_lo + base)     = __nv_bfloat162(l[0], l[1]);
    *(__nv_bfloat162*)(g_lo + base + 2) = __nv_bfloat162(l[2], l[3]);
}

// ---------------------------------------------------------------------------
// Kernel 2: one CTA per tile pair (I,J), I<=J.  HMMA bf16 split-GEMM
// (hi*hi + hi*lo + lo*hi) on the 128x128 block, then dual fused epilogue:
//   epilogue1 -> row sums for rows of I (cols J), written to g_part[J]
//   epilogue2 -> row sums for rows of J (cols I, transposed), to g_part[I]
// Masks and exp values are shared (sim and masks are symmetric).
// ---------------------------------------------------------------------------
__device__ __forceinline__ void fill_tile(char* smem, int off,
                                          const __nv_bfloat16* __restrict__ src,
                                          int rowbase, int tid) {
    #pragma unroll
    for (int it = 0; it < 8; it++) {
        int lin = it * 256 + tid;          // 0..2047
        int n   = lin >> 4;                // tile row 0..127
        int c16 = lin & 15;                // 16B chunk along k
        uint4 v = *(const uint4*)(src + (size_t)(rowbase + n) * DD + c16 * 8);
        *(uint4*)(smem + off + n * 256 + ((c16 ^ (n & 7)) << 4)) = v;
    }
}

__global__ void __launch_bounds__(256, 1)
k_main(const float* __restrict__ d_temp,
       const int*   __restrict__ targets,
       const int*   __restrict__ batch0) {
    extern __shared__ char smem[];
    const uint32_t sb = smem_u32(smem);
    const int tid = threadIdx.x;
    const int L   = tid & 31;
    const int w   = tid >> 5;
    const int wm  = w & 1;          // 0..1 (m)
    const int wn  = w >> 1;         // 0..3 (n)

    // Decode blockIdx.x -> (I, J), I <= J
    int p = blockIdx.x, I = 0;
    while (p >= ITILES - I) { p -= ITILES - I; I++; }
    const int J = I + p;
    const int Ibase = I * 128;
    const int Jbase = J * 128;
    const bool diag = (I == J);

    int*   sm_ti = (int*)(smem + OFF_TI);
    int*   sm_bi = (int*)(smem + OFF_BI);
    int*   sm_tj = (int*)(smem + OFF_TJ);
    int*   sm_bj = (int*)(smem + OFF_BJ);
    float* red1  = (float*)(smem + OFF_RED1);
    float* red2  = (float*)(smem + OFF_RED2);

    const float t     = fminf(fmaxf(d_temp[0], 0.1f), 1.0f);
    const float inv_t = 1.0f / t;

    fill_tile(smem, OFF_AHI, g_hi, Ibase, tid);
    fill_tile(smem, OFF_ALO, g_lo, Ibase, tid);
    fill_tile(smem, OFF_BHI, g_hi, Jbase, tid);
    fill_tile(smem, OFF_BLO, g_lo, Jbase, tid);
    if (tid < 128) {
        sm_ti[tid] = targets[Ibase + tid];
        sm_bi[tid] = batch0[Ibase + tid];
    } else {
        int r = tid - 128;
        sm_tj[r] = targets[Jbase + r];
        sm_bj[r] = batch0[Jbase + r];
    }
    __syncthreads();

    // ---- 3-pass HMMA on the 128x128 block ----
    const int la15 = L & 15;
    const int l4   = L >> 4;
    const int lb7  = (L & 7) + ((L >> 4) << 3);
    const int lb1  = (L >> 3) & 1;

    float acc[4][4][4];
    #pragma unroll
    for (int mi = 0; mi < 4; mi++)
        #pragma unroll
        for (int ni = 0; ni < 4; ni++)
            #pragma unroll
            for (int e = 0; e < 4; e++) acc[mi][ni][e] = 0.f;

    #pragma unroll
    for (int pass = 0; pass < 3; pass++) {
        const uint32_t abase = sb + ((pass == 2) ? OFF_ALO : OFF_AHI);
        const uint32_t bbase = sb + ((pass == 1) ? OFF_BLO : OFF_BHI);
        #pragma unroll
        for (int ks = 0; ks < 8; ks++) {
            uint32_t a[4][4], b[2][4];
            #pragma unroll
            for (int mi = 0; mi < 4; mi++) {
                int rowA = wm * 64 + mi * 16 + la15;
                uint32_t ad = abase + rowA * 256 + (((ks * 2 + l4) ^ (rowA & 7)) << 4);
                LDSM_X4(a[mi][0], a[mi][1], a[mi][2], a[mi][3], ad);
            }
            #pragma unroll
            for (int np = 0; np < 2; np++) {
                int rowB = wn * 32 + np * 16 + lb7;
                uint32_t bd = bbase + rowB * 256 + (((ks * 2 + lb1) ^ (rowB & 7)) << 4);
                LDSM_X4(b[np][0], b[np][1], b[np][2], b[np][3], bd);
            }
            #pragma unroll
            for (int mi = 0; mi < 4; mi++)
                #pragma unroll
                for (int ni = 0; ni < 4; ni++)
                    MMA_BF16(acc[mi][ni], a[mi],
                             b[ni >> 1][(ni & 1) * 2], b[ni >> 1][(ni & 1) * 2 + 1]);
        }
    }

    // ---- Dual fused epilogue ----
    const int g = L >> 2, q = L & 3;
    float pt1[8], nt1[8], pb1[8], nb1[8];   // rows of I (index p1 = mi*2 + (e>>1))
    float pt2[8], nt2[8], pb2[8], nb2[8];   // rows of J (index p2 = ni*2 + (e&1))
    #pragma unroll
    for (int k = 0; k < 8; k++) {
        pt1[k]=nt1[k]=pb1[k]=nb1[k]=0.f;
        pt2[k]=nt2[k]=pb2[k]=nb2[k]=0.f;
    }

    #pragma unroll
    for (int mi = 0; mi < 4; mi++) {
        #pragma unroll
        for (int ni = 0; ni < 4; ni++) {
            #pragma unroll
            for (int e = 0; e < 4; e++) {
                int i_loc = wm * 64 + mi * 16 + (e >> 1) * 8 + g;
                int j_loc = wn * 32 + ni * 8 + 2 * q + (e & 1);
                int p1 = mi * 2 + (e >> 1);
                int p2 = ni * 2 + (e & 1);
                float s  = acc[mi][ni][e];
                float et = __expf(s * inv_t);
                bool same_t = (sm_ti[i_loc] == sm_tj[j_loc]);
                bool self   = diag && (i_loc == j_loc);
                if (same_t) {
                    if (!self) {
                        float eb = __expf(s * 2.0f);   // 1/TEMP_BATCH
                        bool same_b = (sm_bi[i_loc] == sm_bj[j_loc]);
                        pt1[p1] += et; pt2[p2] += et;
                        if (same_b) { pb1[p1] += eb; pb2[p2] += eb; }
                        else        { nb1[p1] += eb; nb2[p2] += eb; }
                    }
                } else {
                    nt1[p1] += et; nt2[p2] += et;
                }
            }
        }
    }

    // ---- Reduction 1: rows of I.  Sum over q lanes, then over wn warps.
    #pragma unroll
    for (int k = 0; k < 8; k++) {
        float a = pt1[k], b = nt1[k], c = pb1[k], d = nb1[k];
        #pragma unroll
        for (int o = 1; o <= 2; o <<= 1) {
            a += __shfl_xor_sync(0xffffffffu, a, o);
            b += __shfl_xor_sync(0xffffffffu, b, o);
            c += __shfl_xor_sync(0xffffffffu, c, o);
            d += __shfl_xor_sync(0xffffffffu, d, o);
        }
        if (q == 0) {
            int row_loc = wm * 64 + (k >> 1) * 16 + (k & 1) * 8 + g;
            *(float4*)&red1[(wn * 128 + row_loc) * 4] = make_float4(a, b, c, d);
        }
    }
    // ---- Reduction 2: rows of J.  Sum over g lanes, then over wm warps.
    if (!diag) {
        #pragma unroll
        for (int k = 0; k < 8; k++) {
            float a = pt2[k], b = nt2[k], c = pb2[k], d = nb2[k];
            #pragma unroll
            for (int o = 4; o <= 16; o <<= 1) {
                a += __shfl_xor_sync(0xffffffffu, a, o);
                b += __shfl_xor_sync(0xffffffffu, b, o);
                c += __shfl_xor_sync(0xffffffffu, c, o);
                d += __shfl_xor_sync(0xffffffffu, d, o);
            }
            if (g == 0) {
                int row_loc = wn * 32 + (k >> 1) * 8 + 2 * q + (k & 1);
                *(float4*)&red2[(wm * 128 + row_loc) * 4] = make_float4(a, b, c, d);
            }
        }
    }
    __syncthreads();

    if (tid < 128) {
        float a = 0.f, b = 0.f, c = 0.f, d = 0.f;
        #pragma unroll
        for (int v = 0; v < 4; v++) {
            float4 r4 = *(const float4*)&red1[(v * 128 + tid) * 4];
            a += r4.x; b += r4.y; c += r4.z; d += r4.w;
        }
        *(float4*)(g_part + ((size_t)J * NN + Ibase + tid) * 4) = make_float4(a, b, c, d);
    } else if (!diag) {
        int r = tid - 128;
        float4 r0 = *(const float4*)&red2[(r) * 4];
        float4 r1 = *(const float4*)&red2[(128 + r) * 4];
        *(float4*)(g_part + ((size_t)I * NN + Jbase + r) * 4) =
            make_float4(r0.x + r1.x, r0.y + r1.y, r0.z + r1.z, r0.w + r1.w);
    }
}

// ---------------------------------------------------------------------------
// Kernel 3: histograms, per-row loss, deterministic class means, final scalar.
// ---------------------------------------------------------------------------
__global__ void k_final(const float* __restrict__ w_t,
                        const float* __restrict__ w_b,
                        const int*   __restrict__ targets,
                        const int*   __restrict__ batch0,
                        float*       __restrict__ out) {
    __shared__ int   hist_t[NCLS];
    __shared__ int   hist_tb[NCLS * NB];
    __shared__ float cls_sum_t[NCLS], cls_cnt_t[NCLS];
    __shared__ float cls_sum_b[NB],   cls_cnt_b[NB];

    int tid = threadIdx.x;
    if (tid < NCLS)      hist_t[tid]  = 0;
    if (tid < NCLS * NB) hist_tb[tid] = 0;
    __syncthreads();

    for (int i = tid; i < NN; i += blockDim.x) {
        int tcl = targets[i], bcl = batch0[i];
        atomicAdd(&hist_t[tcl], 1);
        atomicAdd(&hist_tb[tcl * NB + bcl], 1);
    }
    __syncthreads();

    for (int i = tid; i < NN; i += blockDim.x) {
        float ptv = 0.f, ntv = 0.f, pbv = 0.f, nbv = 0.f;
        #pragma unroll 8
        for (int s = 0; s < JSPLIT; s++) {
            float4 v = *(const float4*)(g_part + ((size_t)s * NN + i) * 4);
            ptv += v.x; ntv += v.y; pbv += v.z; nbv += v.w;
        }
        int tcl = targets[i], bcl = batch0[i];
        int cp = hist_t[tcl];
        int cn = NN - cp;
        bool valid_t = (cp >= 2) && (cn >= 1);
        g_loss_t[i] = valid_t ? logf((ptv + ntv) / ptv) : 0.0f;

        int cpb = hist_tb[tcl * NB + bcl];
        int cnb = cp - cpb;
        bool valid_b = (cpb >= 2) && (cnb >= 1);
        float lbr = logf((pbv + nbv) / pbv);
        g_loss_b[i] = valid_b ? (1.0f / lbr) : 0.0f;
    }
    __syncthreads();

    int wid = tid >> 5, lane = tid & 31;
    if (wid < NCLS) {
        int cp = hist_t[wid];
        bool valid = (cp >= 2) && ((NN - cp) >= 1);
        float s = 0.f, c = 0.f;
        for (int i = lane; i < NN; i += 32) {
            if (targets[i] == wid && valid) { s += g_loss_t[i]; c += 1.0f; }
        }
        #pragma unroll
        for (int o = 16; o; o >>= 1) {
            s += __shfl_xor_sync(0xffffffffu, s, o);
            c += __shfl_xor_sync(0xffffffffu, c, o);
        }
        if (lane == 0) { cls_sum_t[wid] = s; cls_cnt_t[wid] = c; }
    } else if (wid < NCLS + NB) {
        int bc = wid - NCLS;
        float s = 0.f, c = 0.f;
        for (int i = lane; i < NN; i += 32) {
            if (batch0[i] == bc) {
                int tcl = targets[i];
                int cpb = hist_tb[tcl * NB + bc];
                int cnb = hist_t[tcl] - cpb;
                bool valid = (cpb >= 2) && (cnb >= 1);
                if (valid) { s += g_loss_b[i]; c += 1.0f; }
            }
        }
        #pragma unroll
        for (int o = 16; o; o >>= 1) {
            s += __shfl_xor_sync(0xffffffffu, s, o);
            c += __shfl_xor_sync(0xffffffffu, c, o);
        }
        if (lane == 0) { cls_sum_b[bc] = s; cls_cnt_b[bc] = c; }
    }
    __syncthreads();

    if (tid == 0) {
        float lt = 0.f;
        for (int cI = 0; cI < NCLS; cI++) {
            float cnt  = cls_cnt_t[cI];
            float mean = cls_sum_t[cI] / fmaxf(cnt, 1.0f);
            if (cnt > 0.f) lt += mean * w_t[cI];
        }
        float lb = 0.f;
        for (int cI = 0; cI < NB; cI++) {
            float cnt  = cls_cnt_b[cI];
            float mean = cls_sum_b[cI] / fmaxf(cnt, 1.0f);
            if (cnt > 0.f) lb += mean * w_b[cI];
        }
        out[0] = 0.9f * lt + 0.1f * lb;
    }
}

// ---------------------------------------------------------------------------
extern "C" void kernel_launch(void* const* d_in, const int* in_sizes, int n_in,
                              void* d_out, int out_size) {
    const float* x       = (const float*)d_in[0];
    const float* temp    = (const float*)d_in[1];
    const float* w_t     = (const float*)d_in[2];
    const float* w_b     = (const float*)d_in[3];
    const int*   targets = (const int*)d_in[4];
    const int*   batch0  = (const int*)d_in[5];
    float*       out     = (float*)d_out;

    k_norm<<<NN / 8, 256>>>(x);

    cudaFuncSetAttribute(k_main, cudaFuncAttributeMaxDynamicSharedMemorySize, SMEM_TOTAL);
    k_main<<<NPAIRS, 256, SMEM_TOTAL>>>(temp, targets, batch0);

    k_final<<<1, 1024>>>(w_t, w_b, targets, batch0, out);
}

// round 6
// speedup vs baseline: 3.2847x; 1.6887x over previous
#include <cuda_runtime.h>
#include <cuda_fp16.h>
#include <math.h>
#include <stdint.h>

// Problem constants
#define NN    6144
#define DD    128
#define NCLS  20
#define NB    5

#define ITILES 48                     // 6144/128
#define NPAIRS (ITILES*(ITILES+1)/2)  // 1176 tile pairs (I<=J)
#define JSPLIT ITILES                 // one partial buffer per peer tile

// SMEM layout. Tile rows = 256B (128 fp16), 16B-chunk XOR swizzle.
#define OFF_A    0                    // 32KB
#define OFF_B    32768                // 32KB
#define OFF_TI   65536
#define OFF_BI   (OFF_TI + 512)
#define OFF_TJ   (OFF_BI + 512)
#define OFF_BJ   (OFF_TJ + 512)
// RED buffers aliased onto the A tile (dead after MMA) with a syncthreads.
#define OFF_RED1 OFF_A                // 4(wn) x 128 x float4 = 8KB
#define OFF_RED2 (OFF_A + 8192)      // 2(wm) x 128 x float4 = 4KB
#define SMEM_TOTAL (OFF_BJ + 512)     // ~67.5KB

__device__ __forceinline__ uint32_t smem_u32(const void* p) {
    uint32_t a;
    asm("{ .reg .u64 t; cvta.to.shared.u64 t, %1; cvt.u32.u64 %0, t; }" : "=r"(a) : "l"(p));
    return a;
}

#define LDSM_X4(r0, r1, r2, r3, addr) \
    asm volatile("ldmatrix.sync.aligned.m8n8.x4.shared.b16 {%0,%1,%2,%3}, [%4];" \
                 : "=r"(r0), "=r"(r1), "=r"(r2), "=r"(r3) : "r"(addr))

#define MMA_F16(c, a, b0, b1) \
    asm volatile("mma.sync.aligned.m16n8k16.row.col.f32.f16.f16.f32 " \
                 "{%0,%1,%2,%3}, {%4,%5,%6,%7}, {%8,%9}, {%0,%1,%2,%3};" \
                 : "+f"((c)[0]), "+f"((c)[1]), "+f"((c)[2]), "+f"((c)[3]) \
                 : "r"((a)[0]), "r"((a)[1]), "r"((a)[2]), "r"((a)[3]), "r"(b0), "r"(b1))

// ---------------- Scratch (device globals) ----------------
__device__ __half g_h[NN * DD];
__device__ float g_part[JSPLIT * NN * 4];
__device__ float g_sum[NN * 4];
__device__ float g_loss_t[NN];
__device__ float g_loss_b[NN];

// ---------------------------------------------------------------------------
// Kernel 1: normalize + fp16 convert.  One warp per row.
// ---------------------------------------------------------------------------
__global__ void k_norm(const float* __restrict__ x) {
    int row  = blockIdx.x * 8 + (threadIdx.x >> 5);
    int lane = threadIdx.x & 31;
    if (row >= NN) return;
    float4 v = *(const float4*)(x + (size_t)row * DD + lane * 4);
    float s = v.x * v.x + v.y * v.y + v.z * v.z + v.w * v.w;
    #pragma unroll
    for (int o = 16; o; o >>= 1) s += __shfl_xor_sync(0xffffffffu, s, o);
    float inv = 1.0f / fmaxf(sqrtf(s), 1e-8f);
    __half2 h0 = __floats2half2_rn(v.x * inv, v.y * inv);
    __half2 h1 = __floats2half2_rn(v.z * inv, v.w * inv);
    size_t base = (size_t)row * DD + lane * 4;
    *(__half2*)(g_h + base)     = h0;
    *(__half2*)(g_h + base + 2) = h1;
}

// ---------------------------------------------------------------------------
// Kernel 2: one CTA per tile pair (I,J), I<=J.  fp16 HMMA on the 128x128
// block (single pass), dual fused epilogue (rows of I -> g_part[J],
// rows of J transposed -> g_part[I]).
// ---------------------------------------------------------------------------
__device__ __forceinline__ void fill_tile(char* smem, int off,
                                          const __half* __restrict__ src,
                                          int rowbase, int tid) {
    #pragma unroll
    for (int it = 0; it < 8; it++) {
        int lin = it * 256 + tid;          // 0..2047
        int n   = lin >> 4;                // tile row 0..127
        int c16 = lin & 15;                // 16B chunk along k
        uint4 v = *(const uint4*)(src + (size_t)(rowbase + n) * DD + c16 * 8);
        *(uint4*)(smem + off + n * 256 + ((c16 ^ (n & 7)) << 4)) = v;
    }
}

__global__ void __launch_bounds__(256, 1)
k_main(const float* __restrict__ d_temp,
       const int*   __restrict__ targets,
       const int*   __restrict__ batch0) {
    extern __shared__ char smem[];
    const uint32_t sb = smem_u32(smem);
    const int tid = threadIdx.x;
    const int L   = tid & 31;
    const int w   = tid >> 5;
    const int wm  = w & 1;          // 0..1 (m)
    const int wn  = w >> 1;         // 0..3 (n)

    // Decode blockIdx.x -> (I, J), I <= J
    int p = blockIdx.x, I = 0;
    while (p >= ITILES - I) { p -= ITILES - I; I++; }
    const int J = I + p;
    const int Ibase = I * 128;
    const int Jbase = J * 128;
    const bool diag = (I == J);

    int*   sm_ti = (int*)(smem + OFF_TI);
    int*   sm_bi = (int*)(smem + OFF_BI);
    int*   sm_tj = (int*)(smem + OFF_TJ);
    int*   sm_bj = (int*)(smem + OFF_BJ);
    float* red1  = (float*)(smem + OFF_RED1);
    float* red2  = (float*)(smem + OFF_RED2);

    const float t     = fminf(fmaxf(d_temp[0], 0.1f), 1.0f);
    const float inv_t = 1.0f / t;

    fill_tile(smem, OFF_A, g_h, Ibase, tid);
    fill_tile(smem, OFF_B, g_h, Jbase, tid);
    if (tid < 128) {
        sm_ti[tid] = targets[Ibase + tid];
        sm_bi[tid] = batch0[Ibase + tid];
    } else {
        int r = tid - 128;
        sm_tj[r] = targets[Jbase + r];
        sm_bj[r] = batch0[Jbase + r];
    }
    __syncthreads();

    // ---- single-pass fp16 HMMA over K=128 ----
    const int la15 = L & 15;
    const int l4   = L >> 4;
    const int lb7  = (L & 7) + ((L >> 4) << 3);
    const int lb1  = (L >> 3) & 1;

    float acc[4][4][4];
    #pragma unroll
    for (int mi = 0; mi < 4; mi++)
        #pragma unroll
        for (int ni = 0; ni < 4; ni++)
            #pragma unroll
            for (int e = 0; e < 4; e++) acc[mi][ni][e] = 0.f;

    #pragma unroll
    for (int ks = 0; ks < 8; ks++) {
        uint32_t a[4][4], b[2][4];
        #pragma unroll
        for (int mi = 0; mi < 4; mi++) {
            int rowA = wm * 64 + mi * 16 + la15;
            uint32_t ad = sb + OFF_A + rowA * 256 + (((ks * 2 + l4) ^ (rowA & 7)) << 4);
            LDSM_X4(a[mi][0], a[mi][1], a[mi][2], a[mi][3], ad);
        }
        #pragma unroll
        for (int np = 0; np < 2; np++) {
            int rowB = wn * 32 + np * 16 + lb7;
            uint32_t bd = sb + OFF_B + rowB * 256 + (((ks * 2 + lb1) ^ (rowB & 7)) << 4);
            LDSM_X4(b[np][0], b[np][1], b[np][2], b[np][3], bd);
        }
        #pragma unroll
        for (int mi = 0; mi < 4; mi++)
            #pragma unroll
            for (int ni = 0; ni < 4; ni++)
                MMA_F16(acc[mi][ni], a[mi],
                        b[ni >> 1][(ni & 1) * 2], b[ni >> 1][(ni & 1) * 2 + 1]);
    }

    // ---- Dual fused epilogue ----
    const int g = L >> 2, q = L & 3;
    float pt1[8], nt1[8], pb1[8], nb1[8];   // rows of I
    float pt2[8], nt2[8], pb2[8], nb2[8];   // rows of J
    #pragma unroll
    for (int k = 0; k < 8; k++) {
        pt1[k]=nt1[k]=pb1[k]=nb1[k]=0.f;
        pt2[k]=nt2[k]=pb2[k]=nb2[k]=0.f;
    }

    #pragma unroll
    for (int mi = 0; mi < 4; mi++) {
        #pragma unroll
        for (int ni = 0; ni < 4; ni++) {
            #pragma unroll
            for (int e = 0; e < 4; e++) {
                int i_loc = wm * 64 + mi * 16 + (e >> 1) * 8 + g;
                int j_loc = wn * 32 + ni * 8 + 2 * q + (e & 1);
                int p1 = mi * 2 + (e >> 1);
                int p2 = ni * 2 + (e & 1);
                float s  = acc[mi][ni][e];
                float et = __expf(s * inv_t);
                bool same_t = (sm_ti[i_loc] == sm_tj[j_loc]);
                bool self   = diag && (i_loc == j_loc);
                if (same_t) {
                    if (!self) {
                        float eb = __expf(s * 2.0f);   // 1/TEMP_BATCH
                        bool same_b = (sm_bi[i_loc] == sm_bj[j_loc]);
                        pt1[p1] += et; pt2[p2] += et;
                        if (same_b) { pb1[p1] += eb; pb2[p2] += eb; }
                        else        { nb1[p1] += eb; nb2[p2] += eb; }
                    }
                } else {
                    nt1[p1] += et; nt2[p2] += et;
                }
            }
        }
    }

    __syncthreads();   // A/B tiles dead; RED aliases A region

    // ---- Reduction 1: rows of I (sum q lanes, then wn warps via smem)
    #pragma unroll
    for (int k = 0; k < 8; k++) {
        float a = pt1[k], b = nt1[k], c = pb1[k], d = nb1[k];
        #pragma unroll
        for (int o = 1; o <= 2; o <<= 1) {
            a += __shfl_xor_sync(0xffffffffu, a, o);
            b += __shfl_xor_sync(0xffffffffu, b, o);
            c += __shfl_xor_sync(0xffffffffu, c, o);
            d += __shfl_xor_sync(0xffffffffu, d, o);
        }
        if (q == 0) {
            int row_loc = wm * 64 + (k >> 1) * 16 + (k & 1) * 8 + g;
            *(float4*)&red1[(wn * 128 + row_loc) * 4] = make_float4(a, b, c, d);
        }
    }
    // ---- Reduction 2: rows of J (sum g lanes, then wm warps via smem)
    if (!diag) {
        #pragma unroll
        for (int k = 0; k < 8; k++) {
            float a = pt2[k], b = nt2[k], c = pb2[k], d = nb2[k];
            #pragma unroll
            for (int o = 4; o <= 16; o <<= 1) {
                a += __shfl_xor_sync(0xffffffffu, a, o);
                b += __shfl_xor_sync(0xffffffffu, b, o);
                c += __shfl_xor_sync(0xffffffffu, c, o);
                d += __shfl_xor_sync(0xffffffffu, d, o);
            }
            if (g == 0) {
                int row_loc = wn * 32 + (k >> 1) * 8 + 2 * q + (k & 1);
                *(float4*)&red2[(wm * 128 + row_loc) * 4] = make_float4(a, b, c, d);
            }
        }
    }
    __syncthreads();

    if (tid < 128) {
        float a = 0.f, b = 0.f, c = 0.f, d = 0.f;
        #pragma unroll
        for (int v = 0; v < 4; v++) {
            float4 r4 = *(const float4*)&red1[(v * 128 + tid) * 4];
            a += r4.x; b += r4.y; c += r4.z; d += r4.w;
        }
        *(float4*)(g_part + ((size_t)J * NN + Ibase + tid) * 4) = make_float4(a, b, c, d);
    } else if (!diag) {
        int r = tid - 128;
        float4 r0 = *(const float4*)&red2[(r) * 4];
        float4 r1 = *(const float4*)&red2[(128 + r) * 4];
        *(float4*)(g_part + ((size_t)I * NN + Jbase + r) * 4) =
            make_float4(r0.x + r1.x, r0.y + r1.y, r0.z + r1.z, r0.w + r1.w);
    }
}

// ---------------------------------------------------------------------------
// Kernel 2.5: parallel reduction of g_part (48 splits) -> g_sum.  Full chip.
// ---------------------------------------------------------------------------
__global__ void k_reduce() {
    int i = blockIdx.x * 256 + threadIdx.x;   // one row per thread
    if (i >= NN) return;
    float a = 0.f, b = 0.f, c = 0.f, d = 0.f;
    #pragma unroll 8
    for (int s = 0; s < JSPLIT; s++) {
        float4 v = *(const float4*)(g_part + ((size_t)s * NN + i) * 4);
        a += v.x; b += v.y; c += v.z; d += v.w;
    }
    *(float4*)(g_sum + (size_t)i * 4) = make_float4(a, b, c, d);
}

// ---------------------------------------------------------------------------
// Kernel 3: histograms, per-row loss, deterministic class means, final scalar.
// ---------------------------------------------------------------------------
__global__ void k_final(const float* __restrict__ w_t,
                        const float* __restrict__ w_b,
                        const int*   __restrict__ targets,
                        const int*   __restrict__ batch0,
                        float*       __restrict__ out) {
    __shared__ int   hist_t[NCLS];
    __shared__ int   hist_tb[NCLS * NB];
    __shared__ float cls_sum_t[NCLS], cls_cnt_t[NCLS];
    __shared__ float cls_sum_b[NB],   cls_cnt_b[NB];

    int tid = threadIdx.x;
    if (tid < NCLS)      hist_t[tid]  = 0;
    if (tid < NCLS * NB) hist_tb[tid] = 0;
    __syncthreads();

    for (int i = tid; i < NN; i += blockDim.x) {
        int tcl = targets[i], bcl = batch0[i];
        atomicAdd(&hist_t[tcl], 1);
        atomicAdd(&hist_tb[tcl * NB + bcl], 1);
    }
    __syncthreads();

    for (int i = tid; i < NN; i += blockDim.x) {
        float4 v = *(const float4*)(g_sum + (size_t)i * 4);
        float ptv = v.x, ntv = v.y, pbv = v.z, nbv = v.w;
        int tcl = targets[i], bcl = batch0[i];
        int cp = hist_t[tcl];
        int cn = NN - cp;
        bool valid_t = (cp >= 2) && (cn >= 1);
        g_loss_t[i] = valid_t ? logf((ptv + ntv) / ptv) : 0.0f;

        int cpb = hist_tb[tcl * NB + bcl];
        int cnb = cp - cpb;
        bool valid_b = (cpb >= 2) && (cnb >= 1);
        float lbr = logf((pbv + nbv) / pbv);
        g_loss_b[i] = valid_b ? (1.0f / lbr) : 0.0f;
    }
    __syncthreads();

    int wid = tid >> 5, lane = tid & 31;
    if (wid < NCLS) {
        int cp = hist_t[wid];
        bool valid = (cp >= 2) && ((NN - cp) >= 1);
        float s = 0.f, c = 0.f;
        for (int i = lane; i < NN; i += 32) {
            if (targets[i] == wid && valid) { s += g_loss_t[i]; c += 1.0f; }
        }
        #pragma unroll
        for (int o = 16; o; o >>= 1) {
            s += __shfl_xor_sync(0xffffffffu, s, o);
            c += __shfl_xor_sync(0xffffffffu, c, o);
        }
        if (lane == 0) { cls_sum_t[wid] = s; cls_cnt_t[wid] = c; }
    } else if (wid < NCLS + NB) {
        int bc = wid - NCLS;
        float s = 0.f, c = 0.f;
        for (int i = lane; i < NN; i += 32) {
            if (batch0[i] == bc) {
                int tcl = targets[i];
                int cpb = hist_tb[tcl * NB + bc];
                int cnb = hist_t[tcl] - cpb;
                bool valid = (cpb >= 2) && (cnb >= 1);
                if (valid) { s += g_loss_b[i]; c += 1.0f; }
            }
        }
        #pragma unroll
        for (int o = 16; o; o >>= 1) {
            s += __shfl_xor_sync(0xffffffffu, s, o);
            c += __shfl_xor_sync(0xffffffffu, c, o);
        }
        if (lane == 0) { cls_sum_b[bc] = s; cls_cnt_b[bc] = c; }
    }
    __syncthreads();

    if (tid == 0) {
        float lt = 0.f;
        for (int cI = 0; cI < NCLS; cI++) {
            float cnt  = cls_cnt_t[cI];
            float mean = cls_sum_t[cI] / fmaxf(cnt, 1.0f);
            if (cnt > 0.f) lt += mean * w_t[cI];
        }
        float lb = 0.f;
        for (int cI = 0; cI < NB; cI++) {
            float cnt  = cls_cnt_b[cI];
            float mean = cls_sum_b[cI] / fmaxf(cnt, 1.0f);
            if (cnt > 0.f) lb += mean * w_b[cI];
        }
        out[0] = 0.9f * lt + 0.1f * lb;
    }
}

// ---------------------------------------------------------------------------
extern "C" void kernel_launch(void* const* d_in, const int* in_sizes, int n_in,
                              void* d_out, int out_size) {
    const float* x       = (const float*)d_in[0];
    const float* temp    = (const float*)d_in[1];
    const float* w_t     = (const float*)d_in[2];
    const float* w_b     = (const float*)d_in[3];
    const int*   targets = (const int*)d_in[4];
    const int*   batch0  = (const int*)d_in[5];
    float*       out     = (float*)d_out;

    k_norm<<<NN / 8, 256>>>(x);

    cudaFuncSetAttribute(k_main, cudaFuncAttributeMaxDynamicSharedMemorySize, SMEM_TOTAL);
    k_main<<<NPAIRS, 256, SMEM_TOTAL>>>(temp, targets, batch0);

    k_reduce<<<NN / 256, 256>>>();
    k_final<<<1, 1024>>>(w_t, w_b, targets, batch0, out);
}

// round 7
// speedup vs baseline: 5.5556x; 1.6914x over previous
#include <cuda_runtime.h>
#include <cuda_fp16.h>
#include <math.h>
#include <stdint.h>

// Problem constants
#define NN    6144
#define DD    128
#define NCLS  20
#define NB    5

#define ITILES 48                     // 6144/128
#define NPAIRS (ITILES*(ITILES+1)/2)  // 1176 tile pairs (I<=J)
#define JSPLIT ITILES

// SMEM layout for k_main. Tile rows = 256B (128 fp16), 16B-chunk XOR swizzle.
#define OFF_A    0                    // 32KB
#define OFF_B    32768                // 32KB
#define OFF_TI   65536
#define OFF_BI   (OFF_TI + 512)
#define OFF_TJ   (OFF_BI + 512)
#define OFF_BJ   (OFF_TJ + 512)
#define OFF_RED1 OFF_A                // aliased onto dead A tile
#define OFF_RED2 (OFF_A + 8192)
#define SMEM_TOTAL (OFF_BJ + 512)     // ~67.5KB -> 2 CTA/SM

__device__ __forceinline__ uint32_t smem_u32(const void* p) {
    uint32_t a;
    asm("{ .reg .u64 t; cvta.to.shared.u64 t, %1; cvt.u32.u64 %0, t; }" : "=r"(a) : "l"(p));
    return a;
}

#define LDSM_X4(r0, r1, r2, r3, addr) \
    asm volatile("ldmatrix.sync.aligned.m8n8.x4.shared.b16 {%0,%1,%2,%3}, [%4];" \
                 : "=r"(r0), "=r"(r1), "=r"(r2), "=r"(r3) : "r"(addr))

#define MMA_F16(c, a, b0, b1) \
    asm volatile("mma.sync.aligned.m16n8k16.row.col.f32.f16.f16.f32 " \
                 "{%0,%1,%2,%3}, {%4,%5,%6,%7}, {%8,%9}, {%0,%1,%2,%3};" \
                 : "+f"((c)[0]), "+f"((c)[1]), "+f"((c)[2]), "+f"((c)[3]) \
                 : "r"((a)[0]), "r"((a)[1]), "r"((a)[2]), "r"((a)[3]), "r"(b0), "r"(b1))

// ---------------- Scratch (device globals) ----------------
__device__ __half g_h[NN * DD];
__device__ float g_part[JSPLIT * NN * 4];
__device__ int   g_hist_t[NCLS];
__device__ int   g_hist_tb[NCLS * NB];
__device__ float g_blk[24 * 32];          // per-block class partials (20 t + 5 b)

// ---------------------------------------------------------------------------
// Kernel 1: normalize + fp16 convert.  One warp per row.
// ---------------------------------------------------------------------------
__global__ void k_norm(const float* __restrict__ x) {
    int row  = blockIdx.x * 8 + (threadIdx.x >> 5);
    int lane = threadIdx.x & 31;
    if (row >= NN) return;
    float4 v = *(const float4*)(x + (size_t)row * DD + lane * 4);
    float s = v.x * v.x + v.y * v.y + v.z * v.z + v.w * v.w;
    #pragma unroll
    for (int o = 16; o; o >>= 1) s += __shfl_xor_sync(0xffffffffu, s, o);
    float inv = 1.0f / fmaxf(sqrtf(s), 1e-8f);
    __half2 h0 = __floats2half2_rn(v.x * inv, v.y * inv);
    __half2 h1 = __floats2half2_rn(v.z * inv, v.w * inv);
    size_t base = (size_t)row * DD + lane * 4;
    *(__half2*)(g_h + base)     = h0;
    *(__half2*)(g_h + base + 2) = h1;
}

// ---------------------------------------------------------------------------
// Kernel 1b: histograms (int atomics -> order independent, deterministic).
// ---------------------------------------------------------------------------
__global__ void k_hist(const int* __restrict__ targets, const int* __restrict__ batch0) {
    __shared__ int ht[NCLS], htb[NCLS * NB];
    int tid = threadIdx.x;
    if (tid < NCLS)      ht[tid]  = 0;
    if (tid < NCLS * NB) htb[tid] = 0;
    __syncthreads();
    for (int i = tid; i < NN; i += blockDim.x) {
        int t = targets[i], b = batch0[i];
        atomicAdd(&ht[t], 1);
        atomicAdd(&htb[t * NB + b], 1);
    }
    __syncthreads();
    if (tid < NCLS)      g_hist_t[tid]  = ht[tid];
    if (tid < NCLS * NB) g_hist_tb[tid] = htb[tid];
}

// ---------------------------------------------------------------------------
// Kernel 2: one CTA per tile pair (I,J), I<=J.  fp16 HMMA + dual fused epilogue.
// ---------------------------------------------------------------------------
__device__ __forceinline__ void fill_tile(char* smem, int off,
                                          const __half* __restrict__ src,
                                          int rowbase, int tid) {
    #pragma unroll
    for (int it = 0; it < 8; it++) {
        int lin = it * 256 + tid;
        int n   = lin >> 4;
        int c16 = lin & 15;
        uint4 v = *(const uint4*)(src + (size_t)(rowbase + n) * DD + c16 * 8);
        *(uint4*)(smem + off + n * 256 + ((c16 ^ (n & 7)) << 4)) = v;
    }
}

__global__ void __launch_bounds__(256, 2)
k_main(const float* __restrict__ d_temp,
       const int*   __restrict__ targets,
       const int*   __restrict__ batch0) {
    extern __shared__ char smem[];
    const uint32_t sb = smem_u32(smem);
    const int tid = threadIdx.x;
    const int L   = tid & 31;
    const int w   = tid >> 5;
    const int wm  = w & 1;
    const int wn  = w >> 1;

    int p = blockIdx.x, I = 0;
    while (p >= ITILES - I) { p -= ITILES - I; I++; }
    const int J = I + p;
    const int Ibase = I * 128;
    const int Jbase = J * 128;
    const bool diag = (I == J);

    int*   sm_ti = (int*)(smem + OFF_TI);
    int*   sm_bi = (int*)(smem + OFF_BI);
    int*   sm_tj = (int*)(smem + OFF_TJ);
    int*   sm_bj = (int*)(smem + OFF_BJ);
    float* red1  = (float*)(smem + OFF_RED1);
    float* red2  = (float*)(smem + OFF_RED2);

    const float t     = fminf(fmaxf(d_temp[0], 0.1f), 1.0f);
    const float inv_t = 1.0f / t;

    fill_tile(smem, OFF_A, g_h, Ibase, tid);
    fill_tile(smem, OFF_B, g_h, Jbase, tid);
    if (tid < 128) {
        sm_ti[tid] = targets[Ibase + tid];
        sm_bi[tid] = batch0[Ibase + tid];
    } else {
        int r = tid - 128;
        sm_tj[r] = targets[Jbase + r];
        sm_bj[r] = batch0[Jbase + r];
    }
    __syncthreads();

    const int la15 = L & 15;
    const int l4   = L >> 4;
    const int lb7  = (L & 7) + ((L >> 4) << 3);
    const int lb1  = (L >> 3) & 1;

    float acc[4][4][4];
    #pragma unroll
    for (int mi = 0; mi < 4; mi++)
        #pragma unroll
        for (int ni = 0; ni < 4; ni++)
            #pragma unroll
            for (int e = 0; e < 4; e++) acc[mi][ni][e] = 0.f;

    #pragma unroll
    for (int ks = 0; ks < 8; ks++) {
        uint32_t a[4][4], b[2][4];
        #pragma unroll
        for (int mi = 0; mi < 4; mi++) {
            int rowA = wm * 64 + mi * 16 + la15;
            uint32_t ad = sb + OFF_A + rowA * 256 + (((ks * 2 + l4) ^ (rowA & 7)) << 4);
            LDSM_X4(a[mi][0], a[mi][1], a[mi][2], a[mi][3], ad);
        }
        #pragma unroll
        for (int np = 0; np < 2; np++) {
            int rowB = wn * 32 + np * 16 + lb7;
            uint32_t bd = sb + OFF_B + rowB * 256 + (((ks * 2 + lb1) ^ (rowB & 7)) << 4);
            LDSM_X4(b[np][0], b[np][1], b[np][2], b[np][3], bd);
        }
        #pragma unroll
        for (int mi = 0; mi < 4; mi++)
            #pragma unroll
            for (int ni = 0; ni < 4; ni++)
                MMA_F16(acc[mi][ni], a[mi],
                        b[ni >> 1][(ni & 1) * 2], b[ni >> 1][(ni & 1) * 2 + 1]);
    }

    const int g = L >> 2, q = L & 3;
    float pt1[8], nt1[8], pb1[8], nb1[8];
    float pt2[8], nt2[8], pb2[8], nb2[8];
    #pragma unroll
    for (int k = 0; k < 8; k++) {
        pt1[k]=nt1[k]=pb1[k]=nb1[k]=0.f;
        pt2[k]=nt2[k]=pb2[k]=nb2[k]=0.f;
    }

    #pragma unroll
    for (int mi = 0; mi < 4; mi++) {
        #pragma unroll
        for (int ni = 0; ni < 4; ni++) {
            #pragma unroll
            for (int e = 0; e < 4; e++) {
                int i_loc = wm * 64 + mi * 16 + (e >> 1) * 8 + g;
                int j_loc = wn * 32 + ni * 8 + 2 * q + (e & 1);
                int p1 = mi * 2 + (e >> 1);
                int p2 = ni * 2 + (e & 1);
                float s  = acc[mi][ni][e];
                float et = __expf(s * inv_t);
                bool same_t = (sm_ti[i_loc] == sm_tj[j_loc]);
                bool self   = diag && (i_loc == j_loc);
                if (same_t) {
                    if (!self) {
                        float eb = __expf(s * 2.0f);
                        bool same_b = (sm_bi[i_loc] == sm_bj[j_loc]);
                        pt1[p1] += et; pt2[p2] += et;
                        if (same_b) { pb1[p1] += eb; pb2[p2] += eb; }
                        else        { nb1[p1] += eb; nb2[p2] += eb; }
                    }
                } else {
                    nt1[p1] += et; nt2[p2] += et;
                }
            }
        }
    }

    __syncthreads();

    #pragma unroll
    for (int k = 0; k < 8; k++) {
        float a = pt1[k], b = nt1[k], c = pb1[k], d = nb1[k];
        #pragma unroll
        for (int o = 1; o <= 2; o <<= 1) {
            a += __shfl_xor_sync(0xffffffffu, a, o);
            b += __shfl_xor_sync(0xffffffffu, b, o);
            c += __shfl_xor_sync(0xffffffffu, c, o);
            d += __shfl_xor_sync(0xffffffffu, d, o);
        }
        if (q == 0) {
            int row_loc = wm * 64 + (k >> 1) * 16 + (k & 1) * 8 + g;
            *(float4*)&red1[(wn * 128 + row_loc) * 4] = make_float4(a, b, c, d);
        }
    }
    if (!diag) {
        #pragma unroll
        for (int k = 0; k < 8; k++) {
            float a = pt2[k], b = nt2[k], c = pb2[k], d = nb2[k];
            #pragma unroll
            for (int o = 4; o <= 16; o <<= 1) {
                a += __shfl_xor_sync(0xffffffffu, a, o);
                b += __shfl_xor_sync(0xffffffffu, b, o);
                c += __shfl_xor_sync(0xffffffffu, c, o);
                d += __shfl_xor_sync(0xffffffffu, d, o);
            }
            if (g == 0) {
                int row_loc = wn * 32 + (k >> 1) * 8 + 2 * q + (k & 1);
                *(float4*)&red2[(wm * 128 + row_loc) * 4] = make_float4(a, b, c, d);
            }
        }
    }
    __syncthreads();

    if (tid < 128) {
        float a = 0.f, b = 0.f, c = 0.f, d = 0.f;
        #pragma unroll
        for (int v = 0; v < 4; v++) {
            float4 r4 = *(const float4*)&red1[(v * 128 + tid) * 4];
            a += r4.x; b += r4.y; c += r4.z; d += r4.w;
        }
        *(float4*)(g_part + ((size_t)J * NN + Ibase + tid) * 4) = make_float4(a, b, c, d);
    } else if (!diag) {
        int r = tid - 128;
        float4 r0 = *(const float4*)&red2[(r) * 4];
        float4 r1 = *(const float4*)&red2[(128 + r) * 4];
        *(float4*)(g_part + ((size_t)I * NN + Jbase + r) * 4) =
            make_float4(r0.x + r1.x, r0.y + r1.y, r0.z + r1.z, r0.w + r1.w);
    }
}

// ---------------------------------------------------------------------------
// Kernel 3: fused tail (24 blocks x 256 thr).  Per row: reduce 48 partials,
// compute losses; then deterministic block-level class partial sums.
// ---------------------------------------------------------------------------
__global__ void k_tail(const int* __restrict__ targets,
                       const int* __restrict__ batch0) {
    __shared__ float sm_lt[256], sm_lb[256];
    __shared__ int   sm_t[256],  sm_b[256];
    __shared__ float sm_p[32][8];      // [class][sub-partial]

    const int tid = threadIdx.x;
    const int i   = blockIdx.x * 256 + tid;

    // reduce partials
    float ptv = 0.f, ntv = 0.f, pbv = 0.f, nbv = 0.f;
    #pragma unroll 8
    for (int s = 0; s < JSPLIT; s++) {
        float4 v = *(const float4*)(g_part + ((size_t)s * NN + i) * 4);
        ptv += v.x; ntv += v.y; pbv += v.z; nbv += v.w;
    }
    int tcl = targets[i], bcl = batch0[i];
    int cp  = g_hist_t[tcl];
    bool valid_t = (cp >= 2) && ((NN - cp) >= 1);
    int cpb = g_hist_tb[tcl * NB + bcl];
    int cnb = cp - cpb;
    bool valid_b = (cpb >= 2) && (cnb >= 1);

    sm_lt[tid] = valid_t ? logf((ptv + ntv) / ptv) : 0.0f;
    sm_lb[tid] = valid_b ? (1.0f / logf((pbv + nbv) / pbv)) : 0.0f;
    sm_t[tid]  = tcl;
    sm_b[tid]  = bcl;
    __syncthreads();

    // deterministic class partial sums: 8 sub-partials per class, fixed order
    int c = tid >> 3, sub = tid & 7;     // c: 0..31, sub: 0..7
    if (c < NCLS + NB) {
        float s = 0.f;
        int base = sub * 32;
        if (c < NCLS) {
            #pragma unroll 8
            for (int k = 0; k < 32; k++)
                if (sm_t[base + k] == c) s += sm_lt[base + k];
        } else {
            int bc = c - NCLS;
            #pragma unroll 8
            for (int k = 0; k < 32; k++)
                if (sm_b[base + k] == bc) s += sm_lb[base + k];
        }
        sm_p[c][sub] = s;
    }
    __syncthreads();
    if (tid < NCLS + NB) {
        float s = 0.f;
        #pragma unroll
        for (int k = 0; k < 8; k++) s += sm_p[tid][k];
        g_blk[blockIdx.x * 32 + tid] = s;
    }
}

// ---------------------------------------------------------------------------
// Kernel 4: final scalar (1 warp).  Counts derived from histograms.
// ---------------------------------------------------------------------------
__global__ void k_fin(const float* __restrict__ w_t,
                      const float* __restrict__ w_b,
                      float* __restrict__ out) {
    int lane = threadIdx.x;
    float contrib = 0.f;
    if (lane < NCLS) {
        int cp = g_hist_t[lane];
        bool valid = (cp >= 2) && ((NN - cp) >= 1);
        float s = 0.f;
        for (int b = 0; b < 24; b++) s += g_blk[b * 32 + lane];
        float cnt = valid ? (float)cp : 0.f;
        float mean = s / fmaxf(cnt, 1.0f);
        if (cnt > 0.f) contrib = 0.9f * mean * w_t[lane];
    } else if (lane < NCLS + NB) {
        int bc = lane - NCLS;
        float s = 0.f;
        for (int b = 0; b < 24; b++) s += g_blk[b * 32 + lane];
        float cnt = 0.f;
        for (int tc = 0; tc < NCLS; tc++) {
            int cpb = g_hist_tb[tc * NB + bc];
            int cnb = g_hist_t[tc] - cpb;
            if ((cpb >= 2) && (cnb >= 1)) cnt += (float)cpb;
        }
        float mean = s / fmaxf(cnt, 1.0f);
        if (cnt > 0.f) contrib = 0.1f * mean * w_b[bc];
    }
    #pragma unroll
    for (int o = 16; o; o >>= 1) contrib += __shfl_xor_sync(0xffffffffu, contrib, o);
    if (lane == 0) out[0] = contrib;
}

// ---------------------------------------------------------------------------
extern "C" void kernel_launch(void* const* d_in, const int* in_sizes, int n_in,
                              void* d_out, int out_size) {
    const float* x       = (const float*)d_in[0];
    const float* temp    = (const float*)d_in[1];
    const float* w_t     = (const float*)d_in[2];
    const float* w_b     = (const float*)d_in[3];
    const int*   targets = (const int*)d_in[4];
    const int*   batch0  = (const int*)d_in[5];
    float*       out     = (float*)d_out;

    k_norm<<<NN / 8, 256>>>(x);
    k_hist<<<1, 256>>>(targets, batch0);

    cudaFuncSetAttribute(k_main, cudaFuncAttributeMaxDynamicSharedMemorySize, SMEM_TOTAL);
    k_main<<<NPAIRS, 256, SMEM_TOTAL>>>(temp, targets, batch0);

    k_tail<<<NN / 256, 256>>>(targets, batch0);
    k_fin<<<1, 32>>>(w_t, w_b, out);
}

// round 8
// speedup vs baseline: 5.8310x; 1.0496x over previous
#include <cuda_runtime.h>
#include <cuda_fp16.h>
#include <math.h>
#include <stdint.h>

// Problem constants
#define NN    6144
#define DD    128
#define NCLS  20
#define NB    5

#define ITILES 48                     // 6144/128
#define NPAIRS (ITILES*(ITILES+1)/2)  // 1176 tile pairs (I<=J)
#define JSPLIT ITILES

#define TBLK  192                     // k_tail blocks (32 rows each)

// SMEM layout for k_main. Tile rows = 256B (128 fp16), 16B-chunk XOR swizzle.
#define OFF_A    0
#define OFF_B    32768
#define OFF_TI   65536
#define OFF_BI   (OFF_TI + 512)
#define OFF_TJ   (OFF_BI + 512)
#define OFF_BJ   (OFF_TJ + 512)
#define OFF_RED1 OFF_A                // aliased onto dead A tile
#define OFF_RED2 (OFF_A + 8192)
#define SMEM_TOTAL (OFF_BJ + 512)     // ~67.5KB -> 2 CTA/SM

__device__ __forceinline__ uint32_t smem_u32(const void* p) {
    uint32_t a;
    asm("{ .reg .u64 t; cvta.to.shared.u64 t, %1; cvt.u32.u64 %0, t; }" : "=r"(a) : "l"(p));
    return a;
}

#define LDSM_X4(r0, r1, r2, r3, addr) \
    asm volatile("ldmatrix.sync.aligned.m8n8.x4.shared.b16 {%0,%1,%2,%3}, [%4];" \
                 : "=r"(r0), "=r"(r1), "=r"(r2), "=r"(r3) : "r"(addr))

#define MMA_F16(c, a, b0, b1) \
    asm volatile("mma.sync.aligned.m16n8k16.row.col.f32.f16.f16.f32 " \
                 "{%0,%1,%2,%3}, {%4,%5,%6,%7}, {%8,%9}, {%0,%1,%2,%3};" \
                 : "+f"((c)[0]), "+f"((c)[1]), "+f"((c)[2]), "+f"((c)[3]) \
                 : "r"((a)[0]), "r"((a)[1]), "r"((a)[2]), "r"((a)[3]), "r"(b0), "r"(b1))

// ---------------- Scratch (device globals) ----------------
__device__ __half g_h[NN * DD];
__device__ float g_part[JSPLIT * NN * 4];
__device__ int   g_hist_t[NCLS];
__device__ int   g_hist_tb[NCLS * NB];
__device__ float g_blk[TBLK * 32];

// ---------------------------------------------------------------------------
// Kernel 1: normalize + fp16 convert.  One warp per row.
// ---------------------------------------------------------------------------
__global__ void k_norm(const float* __restrict__ x) {
    int row  = blockIdx.x * 8 + (threadIdx.x >> 5);
    int lane = threadIdx.x & 31;
    if (row >= NN) return;
    float4 v = *(const float4*)(x + (size_t)row * DD + lane * 4);
    float s = v.x * v.x + v.y * v.y + v.z * v.z + v.w * v.w;
    #pragma unroll
    for (int o = 16; o; o >>= 1) s += __shfl_xor_sync(0xffffffffu, s, o);
    float inv = 1.0f / fmaxf(sqrtf(s), 1e-8f);
    __half2 h0 = __floats2half2_rn(v.x * inv, v.y * inv);
    __half2 h1 = __floats2half2_rn(v.z * inv, v.w * inv);
    size_t base = (size_t)row * DD + lane * 4;
    *(__half2*)(g_h + base)     = h0;
    *(__half2*)(g_h + base + 2) = h1;
}

// ---------------------------------------------------------------------------
// Kernel 1b: histograms (int atomics -> order independent, deterministic).
// ---------------------------------------------------------------------------
__global__ void k_hist(const int* __restrict__ targets, const int* __restrict__ batch0) {
    __shared__ int ht[NCLS], htb[NCLS * NB];
    int tid = threadIdx.x;
    if (tid < NCLS)      ht[tid]  = 0;
    if (tid < NCLS * NB) htb[tid] = 0;
    __syncthreads();
    for (int i = tid; i < NN; i += blockDim.x) {
        int t = targets[i], b = batch0[i];
        atomicAdd(&ht[t], 1);
        atomicAdd(&htb[t * NB + b], 1);
    }
    __syncthreads();
    if (tid < NCLS)      g_hist_t[tid]  = ht[tid];
    if (tid < NCLS * NB) g_hist_tb[tid] = htb[tid];
}

// ---------------------------------------------------------------------------
// Kernel 2: one CTA per tile pair (I,J), I<=J.  fp16 HMMA + dual fused epilogue.
// ---------------------------------------------------------------------------
__device__ __forceinline__ void fill_tile(char* smem, int off,
                                          const __half* __restrict__ src,
                                          int rowbase, int tid) {
    #pragma unroll
    for (int it = 0; it < 8; it++) {
        int lin = it * 256 + tid;
        int n   = lin >> 4;
        int c16 = lin & 15;
        uint4 v = *(const uint4*)(src + (size_t)(rowbase + n) * DD + c16 * 8);
        *(uint4*)(smem + off + n * 256 + ((c16 ^ (n & 7)) << 4)) = v;
    }
}

__global__ void __launch_bounds__(256, 2)
k_main(const float* __restrict__ d_temp,
       const int*   __restrict__ targets,
       const int*   __restrict__ batch0) {
    extern __shared__ char smem[];
    const uint32_t sb = smem_u32(smem);
    const int tid = threadIdx.x;
    const int L   = tid & 31;
    const int w   = tid >> 5;
    const int wm  = w & 1;
    const int wn  = w >> 1;

    int p = blockIdx.x, I = 0;
    while (p >= ITILES - I) { p -= ITILES - I; I++; }
    const int J = I + p;
    const int Ibase = I * 128;
    const int Jbase = J * 128;
    const bool diag = (I == J);

    int*   sm_ti = (int*)(smem + OFF_TI);
    int*   sm_bi = (int*)(smem + OFF_BI);
    int*   sm_tj = (int*)(smem + OFF_TJ);
    int*   sm_bj = (int*)(smem + OFF_BJ);
    float* red1  = (float*)(smem + OFF_RED1);
    float* red2  = (float*)(smem + OFF_RED2);

    const float t     = fminf(fmaxf(d_temp[0], 0.1f), 1.0f);
    const float inv_t = 1.0f / t;

    fill_tile(smem, OFF_A, g_h, Ibase, tid);
    fill_tile(smem, OFF_B, g_h, Jbase, tid);
    if (tid < 128) {
        sm_ti[tid] = targets[Ibase + tid];
        sm_bi[tid] = batch0[Ibase + tid];
    } else {
        int r = tid - 128;
        sm_tj[r] = targets[Jbase + r];
        sm_bj[r] = batch0[Jbase + r];
    }
    __syncthreads();

    const int la15 = L & 15;
    const int l4   = L >> 4;
    const int lb7  = (L & 7) + ((L >> 4) << 3);
    const int lb1  = (L >> 3) & 1;

    float acc[4][4][4];
    #pragma unroll
    for (int mi = 0; mi < 4; mi++)
        #pragma unroll
        for (int ni = 0; ni < 4; ni++)
            #pragma unroll
            for (int e = 0; e < 4; e++) acc[mi][ni][e] = 0.f;

    #pragma unroll
    for (int ks = 0; ks < 8; ks++) {
        uint32_t a[4][4], b[2][4];
        #pragma unroll
        for (int mi = 0; mi < 4; mi++) {
            int rowA = wm * 64 + mi * 16 + la15;
            uint32_t ad = sb + OFF_A + rowA * 256 + (((ks * 2 + l4) ^ (rowA & 7)) << 4);
            LDSM_X4(a[mi][0], a[mi][1], a[mi][2], a[mi][3], ad);
        }
        #pragma unroll
        for (int np = 0; np < 2; np++) {
            int rowB = wn * 32 + np * 16 + lb7;
            uint32_t bd = sb + OFF_B + rowB * 256 + (((ks * 2 + lb1) ^ (rowB & 7)) << 4);
            LDSM_X4(b[np][0], b[np][1], b[np][2], b[np][3], bd);
        }
        #pragma unroll
        for (int mi = 0; mi < 4; mi++)
            #pragma unroll
            for (int ni = 0; ni < 4; ni++)
                MMA_F16(acc[mi][ni], a[mi],
                        b[ni >> 1][(ni & 1) * 2], b[ni >> 1][(ni & 1) * 2 + 1]);
    }

    const int g = L >> 2, q = L & 3;
    float pt1[8], nt1[8], pb1[8], nb1[8];
    float pt2[8], nt2[8], pb2[8], nb2[8];
    #pragma unroll
    for (int k = 0; k < 8; k++) {
        pt1[k]=nt1[k]=pb1[k]=nb1[k]=0.f;
        pt2[k]=nt2[k]=pb2[k]=nb2[k]=0.f;
    }

    #pragma unroll
    for (int mi = 0; mi < 4; mi++) {
        #pragma unroll
        for (int ni = 0; ni < 4; ni++) {
            #pragma unroll
            for (int e = 0; e < 4; e++) {
                int i_loc = wm * 64 + mi * 16 + (e >> 1) * 8 + g;
                int j_loc = wn * 32 + ni * 8 + 2 * q + (e & 1);
                int p1 = mi * 2 + (e >> 1);
                int p2 = ni * 2 + (e & 1);
                float s  = acc[mi][ni][e];
                float et = __expf(s * inv_t);
                bool same_t = (sm_ti[i_loc] == sm_tj[j_loc]);
                bool self   = diag && (i_loc == j_loc);
                if (same_t) {
                    if (!self) {
                        float eb = __expf(s * 2.0f);
                        bool same_b = (sm_bi[i_loc] == sm_bj[j_loc]);
                        pt1[p1] += et; pt2[p2] += et;
                        if (same_b) { pb1[p1] += eb; pb2[p2] += eb; }
                        else        { nb1[p1] += eb; nb2[p2] += eb; }
                    }
                } else {
                    nt1[p1] += et; nt2[p2] += et;
                }
            }
        }
    }

    __syncthreads();

    #pragma unroll
    for (int k = 0; k < 8; k++) {
        float a = pt1[k], b = nt1[k], c = pb1[k], d = nb1[k];
        #pragma unroll
        for (int o = 1; o <= 2; o <<= 1) {
            a += __shfl_xor_sync(0xffffffffu, a, o);
            b += __shfl_xor_sync(0xffffffffu, b, o);
            c += __shfl_xor_sync(0xffffffffu, c, o);
            d += __shfl_xor_sync(0xffffffffu, d, o);
        }
        if (q == 0) {
            int row_loc = wm * 64 + (k >> 1) * 16 + (k & 1) * 8 + g;
            *(float4*)&red1[(wn * 128 + row_loc) * 4] = make_float4(a, b, c, d);
        }
    }
    if (!diag) {
        #pragma unroll
        for (int k = 0; k < 8; k++) {
            float a = pt2[k], b = nt2[k], c = pb2[k], d = nb2[k];
            #pragma unroll
            for (int o = 4; o <= 16; o <<= 1) {
                a += __shfl_xor_sync(0xffffffffu, a, o);
                b += __shfl_xor_sync(0xffffffffu, b, o);
                c += __shfl_xor_sync(0xffffffffu, c, o);
                d += __shfl_xor_sync(0xffffffffu, d, o);
            }
            if (g == 0) {
                int row_loc = wn * 32 + (k >> 1) * 8 + 2 * q + (k & 1);
                *(float4*)&red2[(wm * 128 + row_loc) * 4] = make_float4(a, b, c, d);
            }
        }
    }
    __syncthreads();

    if (tid < 128) {
        float a = 0.f, b = 0.f, c = 0.f, d = 0.f;
        #pragma unroll
        for (int v = 0; v < 4; v++) {
            float4 r4 = *(const float4*)&red1[(v * 128 + tid) * 4];
            a += r4.x; b += r4.y; c += r4.z; d += r4.w;
        }
        *(float4*)(g_part + ((size_t)J * NN + Ibase + tid) * 4) = make_float4(a, b, c, d);
    } else if (!diag) {
        int r = tid - 128;
        float4 r0 = *(const float4*)&red2[(r) * 4];
        float4 r1 = *(const float4*)&red2[(128 + r) * 4];
        *(float4*)(g_part + ((size_t)I * NN + Jbase + r) * 4) =
            make_float4(r0.x + r1.x, r0.y + r1.y, r0.z + r1.z, r0.w + r1.w);
    }
}

// ---------------------------------------------------------------------------
// Kernel 3: wide tail (192 blocks x 256 thr; 32 rows/block, 8 thr/row).
// Reduce 48 partials per row, compute losses, block-level class partials.
// ---------------------------------------------------------------------------
__global__ void k_tail(const int* __restrict__ targets,
                       const int* __restrict__ batch0) {
    __shared__ float sm_lt[32], sm_lb[32];
    __shared__ int   sm_t[32],  sm_b[32];

    const int tid = threadIdx.x;
    const int rl  = tid >> 3;                 // local row 0..31
    const int s8  = tid & 7;                  // split group 0..7
    const int i   = blockIdx.x * 32 + rl;

    float ptv = 0.f, ntv = 0.f, pbv = 0.f, nbv = 0.f;
    #pragma unroll
    for (int s = s8 * 6; s < s8 * 6 + 6; s++) {
        float4 v = *(const float4*)(g_part + ((size_t)s * NN + i) * 4);
        ptv += v.x; ntv += v.y; pbv += v.z; nbv += v.w;
    }
    #pragma unroll
    for (int o = 1; o <= 4; o <<= 1) {
        ptv += __shfl_xor_sync(0xffffffffu, ptv, o);
        ntv += __shfl_xor_sync(0xffffffffu, ntv, o);
        pbv += __shfl_xor_sync(0xffffffffu, pbv, o);
        nbv += __shfl_xor_sync(0xffffffffu, nbv, o);
    }

    if (s8 == 0) {
        int tcl = targets[i], bcl = batch0[i];
        int cp  = g_hist_t[tcl];
        bool valid_t = (cp >= 2) && ((NN - cp) >= 1);
        int cpb = g_hist_tb[tcl * NB + bcl];
        int cnb = cp - cpb;
        bool valid_b = (cpb >= 2) && (cnb >= 1);
        sm_lt[rl] = valid_t ? logf((ptv + ntv) / ptv) : 0.0f;
        sm_lb[rl] = valid_b ? (1.0f / logf((pbv + nbv) / pbv)) : 0.0f;
        sm_t[rl]  = tcl;
        sm_b[rl]  = bcl;
    }
    __syncthreads();

    // deterministic per-class partials: thread c sums 32 rows in fixed order
    if (tid < NCLS + NB) {
        float s = 0.f;
        if (tid < NCLS) {
            #pragma unroll 8
            for (int k = 0; k < 32; k++)
                if (sm_t[k] == tid) s += sm_lt[k];
        } else {
            int bc = tid - NCLS;
            #pragma unroll 8
            for (int k = 0; k < 32; k++)
                if (sm_b[k] == bc) s += sm_lb[k];
        }
        g_blk[blockIdx.x * 32 + tid] = s;
    }
}

// ---------------------------------------------------------------------------
// Kernel 4: final scalar.  256 threads fold 192 block-partials (fixed order).
// ---------------------------------------------------------------------------
__global__ void k_fin(const float* __restrict__ w_t,
                      const float* __restrict__ w_b,
                      float* __restrict__ out) {
    __shared__ float sm[32][8];
    int tid   = threadIdx.x;
    int c     = tid & 31;
    int chunk = tid >> 5;                    // 0..7, 24 blocks each
    float s = 0.f;
    if (c < NCLS + NB) {
        for (int b = chunk * 24; b < chunk * 24 + 24; b++)
            s += g_blk[b * 32 + c];
    }
    sm[c][chunk] = s;
    __syncthreads();

    if (tid < 32) {
        float tot = 0.f;
        #pragma unroll
        for (int k = 0; k < 8; k++) tot += sm[tid][k];

        float contrib = 0.f;
        if (tid < NCLS) {
            int cp = g_hist_t[tid];
            bool valid = (cp >= 2) && ((NN - cp) >= 1);
            float cnt = valid ? (float)cp : 0.f;
            float mean = tot / fmaxf(cnt, 1.0f);
            if (cnt > 0.f) contrib = 0.9f * mean * w_t[tid];
        } else if (tid < NCLS + NB) {
            int bc = tid - NCLS;
            float cnt = 0.f;
            for (int tc = 0; tc < NCLS; tc++) {
                int cpb = g_hist_tb[tc * NB + bc];
                int cnb = g_hist_t[tc] - cpb;
                if ((cpb >= 2) && (cnb >= 1)) cnt += (float)cpb;
            }
            float mean = tot / fmaxf(cnt, 1.0f);
            if (cnt > 0.f) contrib = 0.1f * mean * w_b[bc];
        }
        #pragma unroll
        for (int o = 16; o; o >>= 1) contrib += __shfl_xor_sync(0xffffffffu, contrib, o);
        if (tid == 0) out[0] = contrib;
    }
}

// ---------------------------------------------------------------------------
extern "C" void kernel_launch(void* const* d_in, const int* in_sizes, int n_in,
                              void* d_out, int out_size) {
    const float* x       = (const float*)d_in[0];
    const float* temp    = (const float*)d_in[1];
    const float* w_t     = (const float*)d_in[2];
    const float* w_b     = (const float*)d_in[3];
    const int*   targets = (const int*)d_in[4];
    const int*   batch0  = (const int*)d_in[5];
    float*       out     = (float*)d_out;

    k_norm<<<NN / 8, 256>>>(x);
    k_hist<<<1, 1024>>>(targets, batch0);

    cudaFuncSetAttribute(k_main, cudaFuncAttributeMaxDynamicSharedMemorySize, SMEM_TOTAL);
    k_main<<<NPAIRS, 256, SMEM_TOTAL>>>(temp, targets, batch0);

    k_tail<<<TBLK, 256>>>(targets, batch0);
    k_fin<<<1, 256>>>(w_t, w_b, out);
}

// round 9
// speedup vs baseline: 5.9346x; 1.0178x over previous
#include <cuda_runtime.h>
#include <cuda_fp16.h>
#include <math.h>
#include <stdint.h>

// Problem constants
#define NN    6144
#define DD    128
#define NCLS  20
#define NB    5

#define ITILES 48                     // 6144/128
#define NPAIRS (ITILES*(ITILES+1)/2)  // 1176 tile pairs (I<=J)
#define JSPLIT ITILES

#define TBLK  192                     // k_tail blocks (32 rows each)

// SMEM layout for k_main. Tile rows = 256B (128 fp16), 16B-chunk XOR swizzle.
#define OFF_A    0
#define OFF_B    32768
#define OFF_TI   65536
#define OFF_BI   (OFF_TI + 512)
#define OFF_TJ   (OFF_BI + 512)
#define OFF_BJ   (OFF_TJ + 512)
#define OFF_RED1 OFF_A                // aliased onto dead A tile
#define OFF_RED2 (OFF_A + 8192)
#define SMEM_TOTAL (OFF_BJ + 512)     // ~67.5KB -> 2 CTA/SM

__device__ __forceinline__ uint32_t smem_u32(const void* p) {
    uint32_t a;
    asm("{ .reg .u64 t; cvta.to.shared.u64 t, %1; cvt.u32.u64 %0, t; }" : "=r"(a) : "l"(p));
    return a;
}

#define LDSM_X4(r0, r1, r2, r3, addr) \
    asm volatile("ldmatrix.sync.aligned.m8n8.x4.shared.b16 {%0,%1,%2,%3}, [%4];" \
                 : "=r"(r0), "=r"(r1), "=r"(r2), "=r"(r3) : "r"(addr))

#define MMA_F16(c, a, b0, b1) \
    asm volatile("mma.sync.aligned.m16n8k16.row.col.f32.f16.f16.f32 " \
                 "{%0,%1,%2,%3}, {%4,%5,%6,%7}, {%8,%9}, {%0,%1,%2,%3};" \
                 : "+f"((c)[0]), "+f"((c)[1]), "+f"((c)[2]), "+f"((c)[3]) \
                 : "r"((a)[0]), "r"((a)[1]), "r"((a)[2]), "r"((a)[3]), "r"(b0), "r"(b1))

// ---------------- Scratch (device globals) ----------------
__device__ __half g_h[NN * DD];
__device__ float g_part[NN * JSPLIT * 4];   // [row][split][4] -- row-major!
__device__ int   g_hist_t[NCLS];
__device__ int   g_hist_tb[NCLS * NB];
__device__ float g_blk[TBLK * 32];

// ---------------------------------------------------------------------------
// Kernel 1: normalize + fp16 convert.  Two rows per warp (MLP=2).
// ---------------------------------------------------------------------------
__global__ void k_norm(const float* __restrict__ x) {
    int row0 = blockIdx.x * 16 + (threadIdx.x >> 5) * 2;
    int lane = threadIdx.x & 31;
    float4 v0 = *(const float4*)(x + (size_t)row0 * DD + lane * 4);
    float4 v1 = *(const float4*)(x + (size_t)(row0 + 1) * DD + lane * 4);
    float s0 = v0.x * v0.x + v0.y * v0.y + v0.z * v0.z + v0.w * v0.w;
    float s1 = v1.x * v1.x + v1.y * v1.y + v1.z * v1.z + v1.w * v1.w;
    #pragma unroll
    for (int o = 16; o; o >>= 1) {
        s0 += __shfl_xor_sync(0xffffffffu, s0, o);
        s1 += __shfl_xor_sync(0xffffffffu, s1, o);
    }
    float i0 = 1.0f / fmaxf(sqrtf(s0), 1e-8f);
    float i1 = 1.0f / fmaxf(sqrtf(s1), 1e-8f);
    size_t b0 = (size_t)row0 * DD + lane * 4;
    *(__half2*)(g_h + b0)          = __floats2half2_rn(v0.x * i0, v0.y * i0);
    *(__half2*)(g_h + b0 + 2)      = __floats2half2_rn(v0.z * i0, v0.w * i0);
    *(__half2*)(g_h + b0 + DD)     = __floats2half2_rn(v1.x * i1, v1.y * i1);
    *(__half2*)(g_h + b0 + DD + 2) = __floats2half2_rn(v1.z * i1, v1.w * i1);
}

// ---------------------------------------------------------------------------
// Kernel 1b: histograms (int atomics -> order independent, deterministic).
// ---------------------------------------------------------------------------
__global__ void k_hist(const int* __restrict__ targets, const int* __restrict__ batch0) {
    __shared__ int ht[NCLS], htb[NCLS * NB];
    int tid = threadIdx.x;
    if (tid < NCLS)      ht[tid]  = 0;
    if (tid < NCLS * NB) htb[tid] = 0;
    __syncthreads();
    for (int i = tid; i < NN; i += blockDim.x) {
        int t = targets[i], b = batch0[i];
        atomicAdd(&ht[t], 1);
        atomicAdd(&htb[t * NB + b], 1);
    }
    __syncthreads();
    if (tid < NCLS)      g_hist_t[tid]  = ht[tid];
    if (tid < NCLS * NB) g_hist_tb[tid] = htb[tid];
}

// ---------------------------------------------------------------------------
// Kernel 2: one CTA per tile pair (I,J), I<=J.  fp16 HMMA + dual fused epilogue.
// Epilogue side-1 partials are mi-sliced (8 live regs, reduced per slice)
// to stay under the 128-reg cap at occupancy 2.
// ---------------------------------------------------------------------------
__device__ __forceinline__ void fill_tile(char* smem, int off,
                                          const __half* __restrict__ src,
                                          int rowbase, int tid) {
    #pragma unroll
    for (int it = 0; it < 8; it++) {
        int lin = it * 256 + tid;
        int n   = lin >> 4;
        int c16 = lin & 15;
        uint4 v = *(const uint4*)(src + (size_t)(rowbase + n) * DD + c16 * 8);
        *(uint4*)(smem + off + n * 256 + ((c16 ^ (n & 7)) << 4)) = v;
    }
}

__global__ void __launch_bounds__(256, 2)
k_main(const float* __restrict__ d_temp,
       const int*   __restrict__ targets,
       const int*   __restrict__ batch0) {
    extern __shared__ char smem[];
    const uint32_t sb = smem_u32(smem);
    const int tid = threadIdx.x;
    const int L   = tid & 31;
    const int w   = tid >> 5;
    const int wm  = w & 1;
    const int wn  = w >> 1;

    int p = blockIdx.x, I = 0;
    while (p >= ITILES - I) { p -= ITILES - I; I++; }
    const int J = I + p;
    const int Ibase = I * 128;
    const int Jbase = J * 128;
    const bool diag = (I == J);

    int*   sm_ti = (int*)(smem + OFF_TI);
    int*   sm_bi = (int*)(smem + OFF_BI);
    int*   sm_tj = (int*)(smem + OFF_TJ);
    int*   sm_bj = (int*)(smem + OFF_BJ);
    float* red1  = (float*)(smem + OFF_RED1);
    float* red2  = (float*)(smem + OFF_RED2);

    const float t     = fminf(fmaxf(d_temp[0], 0.1f), 1.0f);
    const float inv_t = 1.0f / t;

    fill_tile(smem, OFF_A, g_h, Ibase, tid);
    fill_tile(smem, OFF_B, g_h, Jbase, tid);
    if (tid < 128) {
        sm_ti[tid] = targets[Ibase + tid];
        sm_bi[tid] = batch0[Ibase + tid];
    } else {
        int r = tid - 128;
        sm_tj[r] = targets[Jbase + r];
        sm_bj[r] = batch0[Jbase + r];
    }
    __syncthreads();

    const int la15 = L & 15;
    const int l4   = L >> 4;
    const int lb7  = (L & 7) + ((L >> 4) << 3);
    const int lb1  = (L >> 3) & 1;

    float acc[4][4][4];
    #pragma unroll
    for (int mi = 0; mi < 4; mi++)
        #pragma unroll
        for (int ni = 0; ni < 4; ni++)
            #pragma unroll
            for (int e = 0; e < 4; e++) acc[mi][ni][e] = 0.f;

    #pragma unroll
    for (int ks = 0; ks < 8; ks++) {
        uint32_t a[4][4], b[2][4];
        #pragma unroll
        for (int mi = 0; mi < 4; mi++) {
            int rowA = wm * 64 + mi * 16 + la15;
            uint32_t ad = sb + OFF_A + rowA * 256 + (((ks * 2 + l4) ^ (rowA & 7)) << 4);
            LDSM_X4(a[mi][0], a[mi][1], a[mi][2], a[mi][3], ad);
        }
        #pragma unroll
        for (int np = 0; np < 2; np++) {
            int rowB = wn * 32 + np * 16 + lb7;
            uint32_t bd = sb + OFF_B + rowB * 256 + (((ks * 2 + lb1) ^ (rowB & 7)) << 4);
            LDSM_X4(b[np][0], b[np][1], b[np][2], b[np][3], bd);
        }
        #pragma unroll
        for (int mi = 0; mi < 4; mi++)
            #pragma unroll
            for (int ni = 0; ni < 4; ni++)
                MMA_F16(acc[mi][ni], a[mi],
                        b[ni >> 1][(ni & 1) * 2], b[ni >> 1][(ni & 1) * 2 + 1]);
    }

    __syncthreads();   // all LDSM reads of A/B done; red buffers (alias A) safe

    const int g = L >> 2, q = L & 3;
    // Side-2 partials (rows of J) stay live across the whole epilogue.
    float pt2[8], nt2[8], pb2[8], nb2[8];
    #pragma unroll
    for (int k = 0; k < 8; k++) { pt2[k]=nt2[k]=pb2[k]=nb2[k]=0.f; }

    // Epilogue, mi-sliced: side-1 partials (2 rows) reduced + stored per slice.
    #pragma unroll
    for (int mi = 0; mi < 4; mi++) {
        float s1[2][4];
        #pragma unroll
        for (int h = 0; h < 2; h++)
            #pragma unroll
            for (int c = 0; c < 4; c++) s1[h][c] = 0.f;

        #pragma unroll
        for (int ni = 0; ni < 4; ni++) {
            #pragma unroll
            for (int e = 0; e < 4; e++) {
                int h     = e >> 1;
                int i_loc = wm * 64 + mi * 16 + h * 8 + g;
                int j_loc = wn * 32 + ni * 8 + 2 * q + (e & 1);
                int p2    = ni * 2 + (e & 1);
                float s  = acc[mi][ni][e];
                float et = __expf(s * inv_t);
                bool same_t = (sm_ti[i_loc] == sm_tj[j_loc]);
                bool self   = diag && (i_loc == j_loc);
                if (same_t) {
                    if (!self) {
                        float eb = __expf(s * 2.0f);   // 1/TEMP_BATCH
                        bool same_b = (sm_bi[i_loc] == sm_bj[j_loc]);
                        s1[h][0] += et; pt2[p2] += et;
                        if (same_b) { s1[h][2] += eb; pb2[p2] += eb; }
                        else        { s1[h][3] += eb; nb2[p2] += eb; }
                    }
                } else {
                    s1[h][1] += et; nt2[p2] += et;
                }
            }
        }
        // reduce this slice's 2 rows over the 4 q-lanes, store to red1
        #pragma unroll
        for (int h = 0; h < 2; h++) {
            float a = s1[h][0], b = s1[h][1], c = s1[h][2], d = s1[h][3];
            #pragma unroll
            for (int o = 1; o <= 2; o <<= 1) {
                a += __shfl_xor_sync(0xffffffffu, a, o);
                b += __shfl_xor_sync(0xffffffffu, b, o);
                c += __shfl_xor_sync(0xffffffffu, c, o);
                d += __shfl_xor_sync(0xffffffffu, d, o);
            }
            if (q == 0) {
                int row_loc = wm * 64 + mi * 16 + h * 8 + g;
                *(float4*)&red1[(wn * 128 + row_loc) * 4] = make_float4(a, b, c, d);
            }
        }
    }

    // Side-2 reduction over g lanes, then wm warps via smem.
    if (!diag) {
        #pragma unroll
        for (int k = 0; k < 8; k++) {
            float a = pt2[k], b = nt2[k], c = pb2[k], d = nb2[k];
            #pragma unroll
            for (int o = 4; o <= 16; o <<= 1) {
                a += __shfl_xor_sync(0xffffffffu, a, o);
                b += __shfl_xor_sync(0xffffffffu, b, o);
                c += __shfl_xor_sync(0xffffffffu, c, o);
                d += __shfl_xor_sync(0xffffffffu, d, o);
            }
            if (g == 0) {
                int row_loc = wn * 32 + (k >> 1) * 8 + 2 * q + (k & 1);
                *(float4*)&red2[(wm * 128 + row_loc) * 4] = make_float4(a, b, c, d);
            }
        }
    }
    __syncthreads();

    if (tid < 128) {
        float a = 0.f, b = 0.f, c = 0.f, d = 0.f;
        #pragma unroll
        for (int v = 0; v < 4; v++) {
            float4 r4 = *(const float4*)&red1[(v * 128 + tid) * 4];
            a += r4.x; b += r4.y; c += r4.z; d += r4.w;
        }
        *(float4*)(g_part + ((size_t)(Ibase + tid) * JSPLIT + J) * 4) = make_float4(a, b, c, d);
    } else if (!diag) {
        int r = tid - 128;
        float4 r0 = *(const float4*)&red2[(r) * 4];
        float4 r1 = *(const float4*)&red2[(128 + r) * 4];
        *(float4*)(g_part + ((size_t)(Jbase + r) * JSPLIT + I) * 4) =
            make_float4(r0.x + r1.x, r0.y + r1.y, r0.z + r1.z, r0.w + r1.w);
    }
}

// ---------------------------------------------------------------------------
// Kernel 3: wide tail (192 blocks x 256 thr; 32 rows/block, 8 thr/row).
// g_part is row-major -> fully coalesced streaming reads.
// ---------------------------------------------------------------------------
__global__ void k_tail(const int* __restrict__ targets,
                       const int* __restrict__ batch0) {
    __shared__ float sm_lt[32], sm_lb[32];
    __shared__ int   sm_t[32],  sm_b[32];

    const int tid = threadIdx.x;
    const int rl  = tid >> 3;                 // local row 0..31
    const int s8  = tid & 7;                  // split group 0..7
    const int i   = blockIdx.x * 32 + rl;

    float ptv = 0.f, ntv = 0.f, pbv = 0.f, nbv = 0.f;
    const float4* base = (const float4*)(g_part + ((size_t)i * JSPLIT + s8 * 6) * 4);
    #pragma unroll
    for (int s = 0; s < 6; s++) {
        float4 v = base[s];
        ptv += v.x; ntv += v.y; pbv += v.z; nbv += v.w;
    }
    #pragma unroll
    for (int o = 1; o <= 4; o <<= 1) {
        ptv += __shfl_xor_sync(0xffffffffu, ptv, o);
        ntv += __shfl_xor_sync(0xffffffffu, ntv, o);
        pbv += __shfl_xor_sync(0xffffffffu, pbv, o);
        nbv += __shfl_xor_sync(0xffffffffu, nbv, o);
    }

    if (s8 == 0) {
        int tcl = targets[i], bcl = batch0[i];
        int cp  = g_hist_t[tcl];
        bool valid_t = (cp >= 2) && ((NN - cp) >= 1);
        int cpb = g_hist_tb[tcl * NB + bcl];
        int cnb = cp - cpb;
        bool valid_b = (cpb >= 2) && (cnb >= 1);
        sm_lt[rl] = valid_t ? logf((ptv + ntv) / ptv) : 0.0f;
        sm_lb[rl] = valid_b ? (1.0f / logf((pbv + nbv) / pbv)) : 0.0f;
        sm_t[rl]  = tcl;
        sm_b[rl]  = bcl;
    }
    __syncthreads();

    if (tid < NCLS + NB) {
        float s = 0.f;
        if (tid < NCLS) {
            #pragma unroll 8
            for (int k = 0; k < 32; k++)
                if (sm_t[k] == tid) s += sm_lt[k];
        } else {
            int bc = tid - NCLS;
            #pragma unroll 8
            for (int k = 0; k < 32; k++)
                if (sm_b[k] == bc) s += sm_lb[k];
        }
        g_blk[blockIdx.x * 32 + tid] = s;
    }
}

// ---------------------------------------------------------------------------
// Kernel 4: final scalar.  256 threads fold 192 block-partials (fixed order).
// ---------------------------------------------------------------------------
__global__ void k_fin(const float* __restrict__ w_t,
                      const float* __restrict__ w_b,
                      float* __restrict__ out) {
    __shared__ float sm[32][8];
    int tid   = threadIdx.x;
    int c     = tid & 31;
    int chunk = tid >> 5;
    float s = 0.f;
    if (c < NCLS + NB) {
        for (int b = chunk * 24; b < chunk * 24 + 24; b++)
            s += g_blk[b * 32 + c];
    }
    sm[c][chunk] = s;
    __syncthreads();

    if (tid < 32) {
        float tot = 0.f;
        #pragma unroll
        for (int k = 0; k < 8; k++) tot += sm[tid][k];

        float contrib = 0.f;
        if (tid < NCLS) {
            int cp = g_hist_t[tid];
            bool valid = (cp >= 2) && ((NN - cp) >= 1);
            float cnt = valid ? (float)cp : 0.f;
            float mean = tot / fmaxf(cnt, 1.0f);
            if (cnt > 0.f) contrib = 0.9f * mean * w_t[tid];
        } else if (tid < NCLS + NB) {
            int bc = tid - NCLS;
            float cnt = 0.f;
            for (int tc = 0; tc < NCLS; tc++) {
                int cpb = g_hist_tb[tc * NB + bc];
                int cnb = g_hist_t[tc] - cpb;
                if ((cpb >= 2) && (cnb >= 1)) cnt += (float)cpb;
            }
            float mean = tot / fmaxf(cnt, 1.0f);
            if (cnt > 0.f) contrib = 0.1f * mean * w_b[bc];
        }
        #pragma unroll
        for (int o = 16; o; o >>= 1) contrib += __shfl_xor_sync(0xffffffffu, contrib, o);
        if (tid == 0) out[0] = contrib;
    }
}

// ---------------------------------------------------------------------------
extern "C" void kernel_launch(void* const* d_in, const int* in_sizes, int n_in,
                              void* d_out, int out_size) {
    const float* x       = (const float*)d_in[0];
    const float* temp    = (const float*)d_in[1];
    const float* w_t     = (const float*)d_in[2];
    const float* w_b     = (const float*)d_in[3];
    const int*   targets = (const int*)d_in[4];
    const int*   batch0  = (const int*)d_in[5];
    float*       out     = (float*)d_out;

    k_norm<<<NN / 16, 256>>>(x);
    k_hist<<<1, 1024>>>(targets, batch0);

    cudaFuncSetAttribute(k_main, cudaFuncAttributeMaxDynamicSharedMemorySize, SMEM_TOTAL);
    k_main<<<NPAIRS, 256, SMEM_TOTAL>>>(temp, targets, batch0);

    k_tail<<<TBLK, 256>>>(targets, batch0);
    k_fin<<<1, 256>>>(w_t, w_b, out);
}